// round 6
// baseline (speedup 1.0000x reference)
#include <cuda_runtime.h>
#include <cstdint>
#include <cstddef>

// Problem shape (fixed by the reference setup_inputs):
//   x: [8192, 4096] fp32, W_router/W_orig: [4096, 4096] fp32 (row-major, K contiguous)
//   out[n,o] = (x @ W_orig^T)[n,o] * topk_mask(x @ W_router^T)[n,o],  k = 1024 per row
#define NTOK 8192
#define DDIM 4096
#define ODIM 4096
#define KSEL 1024

// Scratch for router logits. IMPORTANT: this is a __device__ symbol — it must
// only ever be referenced from DEVICE code. Passing it as a kernel argument
// from host code (kernel_launch) passes the host-side shadow address, which
// is what corrupted runs in Rounds 2-5.
__device__ float g_router[(size_t)NTOK * ODIM];

#define BK 16

// ---------------------------------------------------------------------------
// Fast SGEMM (orig path). Replica of the Round-1 kernel that ran clean
// (launch_bounds(256,2) -> 128-reg cap). 128x128 tile, BK=16, 256 threads,
// 8x8 microtile. Writes to C (the harness's d_out — a real device pointer).
// ---------------------------------------------------------------------------
__global__ __launch_bounds__(256, 2)
void gemm_fast_kernel(const float* __restrict__ x,
                      const float* __restrict__ W,
                      const float* __restrict__ bias,
                      float* __restrict__ C)
{
    __shared__ float As[BK][128];
    __shared__ float Bs[BK][128];

    const int tid = threadIdx.x;
    const int tx = tid & 15;       // 0..15 -> N direction
    const int ty = tid >> 4;       // 0..15 -> M direction

    const int mBase = blockIdx.y * 128;
    const int nBase = blockIdx.x * 128;

    float acc[8][8];
#pragma unroll
    for (int i = 0; i < 8; i++)
#pragma unroll
        for (int j = 0; j < 8; j++) acc[i][j] = 0.0f;

    for (int k0 = 0; k0 < DDIM; k0 += BK) {
#pragma unroll
        for (int l = 0; l < 2; l++) {
            int idx = tid + l * 256;       // 0..511
            int row = idx >> 2;            // 0..127
            int kg  = idx & 3;             // 0..3 (float4 group within BK)
            float4 va = *reinterpret_cast<const float4*>(
                &x[(size_t)(mBase + row) * DDIM + k0 + kg * 4]);
            As[kg * 4 + 0][row] = va.x;
            As[kg * 4 + 1][row] = va.y;
            As[kg * 4 + 2][row] = va.z;
            As[kg * 4 + 3][row] = va.w;
            float4 vb = *reinterpret_cast<const float4*>(
                &W[(size_t)(nBase + row) * DDIM + k0 + kg * 4]);
            Bs[kg * 4 + 0][row] = vb.x;
            Bs[kg * 4 + 1][row] = vb.y;
            Bs[kg * 4 + 2][row] = vb.z;
            Bs[kg * 4 + 3][row] = vb.w;
        }
        __syncthreads();

#pragma unroll
        for (int k = 0; k < BK; k++) {
            float ra[8], rb[8];
            const float4* ap = reinterpret_cast<const float4*>(&As[k][ty * 8]);
            const float4* bp = reinterpret_cast<const float4*>(&Bs[k][tx * 8]);
            float4 a0 = ap[0], a1 = ap[1];
            float4 b0 = bp[0], b1 = bp[1];
            ra[0]=a0.x; ra[1]=a0.y; ra[2]=a0.z; ra[3]=a0.w;
            ra[4]=a1.x; ra[5]=a1.y; ra[6]=a1.z; ra[7]=a1.w;
            rb[0]=b0.x; rb[1]=b0.y; rb[2]=b0.z; rb[3]=b0.w;
            rb[4]=b1.x; rb[5]=b1.y; rb[6]=b1.z; rb[7]=b1.w;
#pragma unroll
            for (int i = 0; i < 8; i++)
#pragma unroll
                for (int j = 0; j < 8; j++)
                    acc[i][j] = fmaf(ra[i], rb[j], acc[i][j]);
        }
        __syncthreads();
    }

#pragma unroll
    for (int i = 0; i < 8; i++) {
        const int row = mBase + ty * 8 + i;
#pragma unroll
        for (int j = 0; j < 8; j += 4) {
            const int col = nBase + tx * 8 + j;
            float4 v;
            v.x = acc[i][j + 0] + bias[col + 0];
            v.y = acc[i][j + 1] + bias[col + 1];
            v.z = acc[i][j + 2] + bias[col + 2];
            v.w = acc[i][j + 3] + bias[col + 3];
            *reinterpret_cast<float4*>(&C[(size_t)row * ODIM + col]) = v;
        }
    }
}

// ---------------------------------------------------------------------------
// Accurate SGEMM (router path): 512 threads, 128x64 tile, 4x4 microtile,
// two-level accumulation (BK=16 chunk sums flushed into the main
// accumulator; shortens the rounding chain 4096 -> 256, cutting router-logit
// noise ~4x — that noise drives top-k boundary swaps, the dominant rel_err
// term). Writes DIRECTLY to the device global g_router (no host-passed
// pointer).
// ---------------------------------------------------------------------------
__global__ __launch_bounds__(512, 1)
void gemm_router_kernel(const float* __restrict__ x,
                        const float* __restrict__ W,
                        const float* __restrict__ bias)
{
    __shared__ float As[BK][128];
    __shared__ float Bs[BK][64];

    const int tid = threadIdx.x;
    const int tx = tid & 15;       // 0..15, x4 -> 64 N
    const int ty = tid >> 4;       // 0..31, x4 -> 128 M
    const int mBase = blockIdx.y * 128;
    const int nBase = blockIdx.x * 64;

    float acc[4][4];
#pragma unroll
    for (int i = 0; i < 4; i++)
#pragma unroll
        for (int j = 0; j < 4; j++) acc[i][j] = 0.0f;

    for (int k0 = 0; k0 < DDIM; k0 += BK) {
        // A tile: 128x16 = 512 float4, one per thread
        {
            int row = tid >> 2;            // 0..127
            int kg  = tid & 3;
            float4 va = *reinterpret_cast<const float4*>(
                &x[(size_t)(mBase + row) * DDIM + k0 + kg * 4]);
            As[kg * 4 + 0][row] = va.x;
            As[kg * 4 + 1][row] = va.y;
            As[kg * 4 + 2][row] = va.z;
            As[kg * 4 + 3][row] = va.w;
        }
        // B tile: 64x16 = 256 float4, threads 0..255
        if (tid < 256) {
            int row = tid >> 2;            // 0..63
            int kg  = tid & 3;
            float4 vb = *reinterpret_cast<const float4*>(
                &W[(size_t)(nBase + row) * DDIM + k0 + kg * 4]);
            Bs[kg * 4 + 0][row] = vb.x;
            Bs[kg * 4 + 1][row] = vb.y;
            Bs[kg * 4 + 2][row] = vb.z;
            Bs[kg * 4 + 3][row] = vb.w;
        }
        __syncthreads();

        float cacc[4][4];
#pragma unroll
        for (int i = 0; i < 4; i++)
#pragma unroll
            for (int j = 0; j < 4; j++) cacc[i][j] = 0.0f;

#pragma unroll
        for (int k = 0; k < BK; k++) {
            float4 a0 = *reinterpret_cast<const float4*>(&As[k][ty * 4]);
            float4 b0 = *reinterpret_cast<const float4*>(&Bs[k][tx * 4]);
            float ra[4], rb[4];
            ra[0]=a0.x; ra[1]=a0.y; ra[2]=a0.z; ra[3]=a0.w;
            rb[0]=b0.x; rb[1]=b0.y; rb[2]=b0.z; rb[3]=b0.w;
#pragma unroll
            for (int i = 0; i < 4; i++)
#pragma unroll
                for (int j = 0; j < 4; j++)
                    cacc[i][j] = fmaf(ra[i], rb[j], cacc[i][j]);
        }

#pragma unroll
        for (int i = 0; i < 4; i++)
#pragma unroll
            for (int j = 0; j < 4; j++) acc[i][j] += cacc[i][j];
        __syncthreads();
    }

#pragma unroll
    for (int i = 0; i < 4; i++) {
        const int row = mBase + ty * 4 + i;
        const int col = nBase + tx * 4;
        float4 v;
        v.x = acc[i][0] + bias[col + 0];
        v.y = acc[i][1] + bias[col + 1];
        v.z = acc[i][2] + bias[col + 2];
        v.w = acc[i][3] + bias[col + 3];
        *reinterpret_cast<float4*>(&g_router[(size_t)row * ODIM + col]) = v;
    }
}

// ---------------------------------------------------------------------------
// Per-row top-k threshold (radix select on order-preserving uint bits)
// + mask application. One block per row; row cached in shared memory.
// Reads g_router as a device global (as in the clean Round-1 run).
// ---------------------------------------------------------------------------
__device__ __forceinline__ unsigned int f2ord(float f) {
    unsigned int b = __float_as_uint(f);
    return (b & 0x80000000u) ? ~b : (b | 0x80000000u);
}

__global__ __launch_bounds__(256)
void topk_mask_kernel(float* __restrict__ out)
{
    __shared__ unsigned int srow[ODIM];   // 16 KB: ordered router bits
    __shared__ unsigned int hist[256];
    __shared__ unsigned int s_prefix;
    __shared__ int s_kk;

    const int row = blockIdx.x;
    const int tid = threadIdx.x;
    const size_t base = (size_t)row * ODIM;

    for (int i = tid; i < ODIM; i += 256)
        srow[i] = f2ord(g_router[base + i]);

    if (tid == 0) { s_prefix = 0u; s_kk = KSEL; }
    __syncthreads();

    // 4 radix passes, MSB -> LSB, 8 bits each. After the last pass,
    // s_prefix holds the exact ordered bits of the k-th largest element.
    for (int shift = 24; shift >= 0; shift -= 8) {
        hist[tid] = 0u;
        __syncthreads();
        const unsigned int prefix = s_prefix;
        const unsigned int maskhi = (shift == 24) ? 0u
                                                  : (0xFFFFFFFFu << (shift + 8));
        for (int i = tid; i < ODIM; i += 256) {
            unsigned int u = srow[i];
            if ((u & maskhi) == prefix)
                atomicAdd(&hist[(u >> shift) & 0xFFu], 1u);
        }
        __syncthreads();
        if (tid == 0) {
            int kk = s_kk;
            int cum = 0;
            int b = 255;
            for (; b >= 0; b--) {
                cum += (int)hist[b];
                if (cum >= kk) break;
            }
            s_kk = kk - (cum - (int)hist[b]);
            s_prefix = prefix | ((unsigned int)b << shift);
        }
        __syncthreads();
    }

    const unsigned int thr = s_prefix;   // ordered bits of k-th largest
    for (int i = tid; i < ODIM; i += 256) {
        if (srow[i] < thr) out[base + i] = 0.0f;
    }
}

// ---------------------------------------------------------------------------
// Harness entry point. NOTE: g_router is never mentioned here — host code
// must not touch a __device__ symbol.
// ---------------------------------------------------------------------------
extern "C" void kernel_launch(void* const* d_in, const int* in_sizes, int n_in,
                              void* d_out, int out_size)
{
    const float* x  = (const float*)d_in[0];
    const float* Wr = (const float*)d_in[1];
    const float* br = (const float*)d_in[2];
    const float* Wo = (const float*)d_in[3];
    const float* bo = (const float*)d_in[4];
    float* out = (float*)d_out;

    gemm_fast_kernel  <<<dim3(ODIM / 128, NTOK / 128), 256>>>(x, Wo, bo, out);
    gemm_router_kernel<<<dim3(ODIM /  64, NTOK / 128), 512>>>(x, Wr, br);
    topk_mask_kernel  <<<NTOK, 256>>>(out);
}

// round 10
// speedup vs baseline: 1.7903x; 1.7903x over previous
#include <cuda_runtime.h>
#include <cstdint>
#include <cstddef>

// Problem shape (fixed by the reference setup_inputs):
//   x: [8192, 4096] fp32, W_router/W_orig: [4096, 4096] fp32 (row-major, K contiguous)
//   out[n,o] = (x @ W_orig^T)[n,o] * topk_mask(x @ W_router^T)[n,o],  k = 1024 per row
#define NTOK 8192
#define DDIM 4096
#define ODIM 4096
#define KSEL 1024

// ---------------------------------------------------------------------------
// Device-global scratch (allocation-free rule). Referenced ONLY from device
// code — never passed as kernel arguments from host (shadow-address bug, R2-5).
// ---------------------------------------------------------------------------
__device__ float g_router[(size_t)NTOK * ODIM];
__device__ float g_xhi[(size_t)NTOK * DDIM];
__device__ float g_xlo[(size_t)NTOK * DDIM];
__device__ float g_wrhi[(size_t)ODIM * DDIM];
__device__ float g_wrlo[(size_t)ODIM * DDIM];
__device__ float g_wohi[(size_t)ODIM * DDIM];
__device__ float g_wolo[(size_t)ODIM * DDIM];

__device__ __forceinline__ uint32_t smem_u32(const void* p) {
    uint32_t a;
    asm("{ .reg .u64 t; cvta.to.shared.u64 t, %1; cvt.u32.u64 %0, t; }"
        : "=r"(a) : "l"(p));
    return a;
}

// tf32 round-to-nearest: destination is a b32 register (fp32 bit layout with
// low 13 mantissa bits zeroed).
__device__ __forceinline__ float tf32_rna(float x) {
    uint32_t r;
    asm("cvt.rna.tf32.f32 %0, %1;" : "=r"(r) : "f"(x));
    return __uint_as_float(r);
}

// Warp-level tf32 MMA: D(16x8,f32) += A(16x8,tf32) * B(8x8,tf32)
#define MMA_TF32(c, a, b) \
    asm volatile( \
        "mma.sync.aligned.m16n8k8.row.col.f32.tf32.tf32.f32 " \
        "{%0,%1,%2,%3}, {%4,%5,%6,%7}, {%8,%9}, {%0,%1,%2,%3};" \
        : "+f"((c)[0]), "+f"((c)[1]), "+f"((c)[2]), "+f"((c)[3]) \
        : "r"((a)[0]), "r"((a)[1]), "r"((a)[2]), "r"((a)[3]), \
          "r"((b)[0]), "r"((b)[1]))

#define CP_ASYNC16(smem_u32_addr, gptr) \
    asm volatile("cp.async.cg.shared.global [%0], [%1], 16;" \
                 :: "r"(smem_u32_addr), "l"(gptr))
#define CP_COMMIT() asm volatile("cp.async.commit_group;" ::: "memory")
#define CP_WAIT1()  asm volatile("cp.async.wait_group 1;" ::: "memory")

// ---------------------------------------------------------------------------
// Split kernel: fp32 -> (tf32 hi, tf32 lo) Dekker split, stored as fp32.
// which: 0 -> x, 1 -> W_router, 2 -> W_orig.
// ---------------------------------------------------------------------------
__global__ __launch_bounds__(256)
void split_kernel(const float* __restrict__ src, int n4, int which)
{
    float* hi;
    float* lo;
    if (which == 0)      { hi = g_xhi;  lo = g_xlo;  }
    else if (which == 1) { hi = g_wrhi; lo = g_wrlo; }
    else                 { hi = g_wohi; lo = g_wolo; }

    const int stride = gridDim.x * blockDim.x;
    for (int i = blockIdx.x * blockDim.x + threadIdx.x; i < n4; i += stride) {
        float4 v = reinterpret_cast<const float4*>(src)[i];
        float4 h, l;
        h.x = tf32_rna(v.x); l.x = tf32_rna(v.x - h.x);
        h.y = tf32_rna(v.y); l.y = tf32_rna(v.y - h.y);
        h.z = tf32_rna(v.z); l.z = tf32_rna(v.z - h.z);
        h.w = tf32_rna(v.w); l.w = tf32_rna(v.w - h.w);
        reinterpret_cast<float4*>(hi)[i] = h;
        reinterpret_cast<float4*>(lo)[i] = l;
    }
}

// ---------------------------------------------------------------------------
// tf32x3 tensor-core GEMM (mma.sync m16n8k8), double-buffered cp.async.
// C = hiA*hiB + hiA*loB + loA*hiB  (+bias)
// which: 0 -> W_orig -> outp (d_out);  1 -> W_router -> g_router
// Block tile 128x128, BK=32, 256 threads = 8 warps (2 M x 4 N).
// ---------------------------------------------------------------------------
#define KITER  (DDIM / 32)
#define TPAD   36
#define TSZ    (128 * TPAD)
#define NT     4                    // tiles per stage: Ahi,Bhi,Alo,Blo
#define GSMEM  (2 * NT * TSZ * 4)   // 147456 B

__global__ __launch_bounds__(256, 1)
void gemm_mma3_kernel(const float* __restrict__ bias,
                      float* __restrict__ outp,
                      int which)
{
    extern __shared__ float smf[];
    const int tid  = threadIdx.x;
    const int wid  = tid >> 5;
    const int lane = tid & 31;
    const int gid  = lane >> 2;
    const int tig  = lane & 3;

    const float* __restrict__ Ahi = g_xhi;
    const float* __restrict__ Alo = g_xlo;
    const float* __restrict__ Bhi = (which == 0) ? g_wohi : g_wrhi;
    const float* __restrict__ Blo = (which == 0) ? g_wolo : g_wrlo;
    float* __restrict__ C = (which == 0) ? outp : g_router;

    const int mBase = blockIdx.y * 128;
    const int nBase = blockIdx.x * 128;
    const int warpM = (wid >> 2) * 64;
    const int warpN = (wid & 3) * 32;

    const uint32_t sb = smem_u32(smf);

    auto load_tile = [&](int stage, int slot, const float* __restrict__ g,
                         int rowBase, int k0) {
        const uint32_t dst = sb + (uint32_t)((stage * NT + slot) * TSZ) * 4u;
#pragma unroll
        for (int t = 0; t < 4; t++) {
            int idx = tid + t * 256;
            int row = idx >> 3;
            int c   = idx & 7;
            const float* src = g + (size_t)(rowBase + row) * DDIM + k0 + c * 4;
            uint32_t d = dst + (uint32_t)(row * TPAD + c * 4) * 4u;
            CP_ASYNC16(d, src);
        }
    };
    auto load_stage = [&](int it, int stage) {
        const int k0 = it * 32;
        load_tile(stage, 0, Ahi, mBase, k0);
        load_tile(stage, 1, Bhi, nBase, k0);
        load_tile(stage, 2, Alo, mBase, k0);
        load_tile(stage, 3, Blo, nBase, k0);
        CP_COMMIT();
    };

    float cfr[4][4][4];
#pragma unroll
    for (int mt = 0; mt < 4; mt++)
#pragma unroll
        for (int nt = 0; nt < 4; nt++)
#pragma unroll
            for (int q = 0; q < 4; q++) cfr[mt][nt][q] = 0.0f;

    load_stage(0, 0);
    load_stage(1, 1);

    for (int it = 0; it < KITER; it++) {
        CP_WAIT1();
        __syncthreads();

        const uint32_t* As  = reinterpret_cast<const uint32_t*>(
                                  smf + (it & 1) * NT * TSZ);
        const uint32_t* Bs  = As + TSZ;
        const uint32_t* Asl = As + 2 * TSZ;
        const uint32_t* Bsl = As + 3 * TSZ;

#pragma unroll
        for (int ks = 0; ks < 4; ks++) {
            const int kk = ks * 8;
            uint32_t ah[4][4], bh[4][2], al[4][4], bl[4][2];
#pragma unroll
            for (int mt = 0; mt < 4; mt++) {
                const int r0 = (warpM + mt * 16 + gid) * TPAD + kk + tig;
                const int r1 = r0 + 8 * TPAD;
                ah[mt][0] = As[r0];      ah[mt][1] = As[r1];
                ah[mt][2] = As[r0 + 4];  ah[mt][3] = As[r1 + 4];
                al[mt][0] = Asl[r0];     al[mt][1] = Asl[r1];
                al[mt][2] = Asl[r0 + 4]; al[mt][3] = Asl[r1 + 4];
            }
#pragma unroll
            for (int nt = 0; nt < 4; nt++) {
                const int rn = (warpN + nt * 8 + gid) * TPAD + kk + tig;
                bh[nt][0] = Bs[rn];  bh[nt][1] = Bs[rn + 4];
                bl[nt][0] = Bsl[rn]; bl[nt][1] = Bsl[rn + 4];
            }
#pragma unroll
            for (int mt = 0; mt < 4; mt++)
#pragma unroll
                for (int nt = 0; nt < 4; nt++) {
                    MMA_TF32(cfr[mt][nt], ah[mt], bh[nt]);
                    MMA_TF32(cfr[mt][nt], ah[mt], bl[nt]);
                    MMA_TF32(cfr[mt][nt], al[mt], bh[nt]);
                }
        }
        __syncthreads();
        if (it + 2 < KITER) load_stage(it + 2, it & 1);
    }

#pragma unroll
    for (int mt = 0; mt < 4; mt++) {
        const int row = mBase + warpM + mt * 16 + gid;
#pragma unroll
        for (int nt = 0; nt < 4; nt++) {
            const int col = nBase + warpN + nt * 8 + tig * 2;
            const float b0 = bias[col], b1 = bias[col + 1];
            float2 v0 = make_float2(cfr[mt][nt][0] + b0, cfr[mt][nt][1] + b1);
            float2 v1 = make_float2(cfr[mt][nt][2] + b0, cfr[mt][nt][3] + b1);
            *reinterpret_cast<float2*>(&C[(size_t)row * ODIM + col]) = v0;
            *reinterpret_cast<float2*>(&C[(size_t)(row + 8) * ODIM + col]) = v1;
        }
    }
}

// ---------------------------------------------------------------------------
// Top-k with exact boundary fixup. One block per row.
//  1. radix-select approx threshold on g_router logits
//  2. logits within +-DELTA of it are rescored EXACTLY (fp64 dot of x.Wr+br)
//  3. keep = above band  U  exact-top of band (exactly KSEL kept)
// Makes the mask exact w.r.t. true fp32 logits for any GEMM noise < DELTA.
// ---------------------------------------------------------------------------
#define DELTA 4e-3f
#define MAXC  128

__device__ __forceinline__ unsigned int f2ord(float f) {
    unsigned int b = __float_as_uint(f);
    return (b & 0x80000000u) ? ~b : (b | 0x80000000u);
}

__global__ __launch_bounds__(256)
void topk_fix_kernel(const float* __restrict__ x,
                     const float* __restrict__ Wr,
                     const float* __restrict__ br,
                     float* __restrict__ out)
{
    __shared__ float xrow[DDIM];            // 16 KB
    __shared__ unsigned int srow[ODIM];     // 16 KB ordered approx logits
    __shared__ unsigned char keep[ODIM];    // 4 KB
    __shared__ unsigned int hist[256];      // 1 KB
    __shared__ int cand_idx[MAXC];          // 512 B
    __shared__ double cscore[MAXC];         // 1 KB
    __shared__ double red[256];             // 2 KB
    __shared__ unsigned int s_prefix;
    __shared__ int s_kk, s_ncand, s_above, s_extra;
    __shared__ unsigned int s_bhi, s_blo;

    const int row = blockIdx.x;
    const int tid = threadIdx.x;
    const size_t base = (size_t)row * ODIM;

    for (int i = tid; i < DDIM; i += 256)
        xrow[i] = x[(size_t)row * DDIM + i];
    for (int i = tid; i < ODIM; i += 256)
        srow[i] = f2ord(g_router[base + i]);

    if (tid == 0) {
        s_prefix = 0u; s_kk = KSEL;
        s_ncand = 0; s_above = 0; s_extra = 0;
    }
    __syncthreads();

    // Radix select: ordered bits of the k-th largest approx logit.
    for (int shift = 24; shift >= 0; shift -= 8) {
        hist[tid] = 0u;
        __syncthreads();
        const unsigned int prefix = s_prefix;
        const unsigned int maskhi = (shift == 24) ? 0u
                                                  : (0xFFFFFFFFu << (shift + 8));
        for (int i = tid; i < ODIM; i += 256) {
            unsigned int u = srow[i];
            if ((u & maskhi) == prefix)
                atomicAdd(&hist[(u >> shift) & 0xFFu], 1u);
        }
        __syncthreads();
        if (tid == 0) {
            int kk = s_kk, cum = 0, b = 255;
            for (; b >= 0; b--) {
                cum += (int)hist[b];
                if (cum >= kk) break;
            }
            s_kk = kk - (cum - (int)hist[b]);
            s_prefix = prefix | ((unsigned int)b << shift);
        }
        __syncthreads();
    }

    const unsigned int thr = s_prefix;
    if (tid == 0) {
        // ordered uint -> float
        unsigned int b = (thr & 0x80000000u) ? (thr & 0x7FFFFFFFu) : ~thr;
        float vthr = __uint_as_float(b);
        s_bhi = f2ord(vthr + DELTA);
        s_blo = f2ord(vthr - DELTA);
    }
    __syncthreads();
    const unsigned int bhi = s_bhi, blo = s_blo;

    // Classify: sure-keep / candidate / drop.
    int my_above = 0;
    for (int i = tid; i < ODIM; i += 256) {
        unsigned int u = srow[i];
        if (u > bhi) {
            keep[i] = 1; my_above++;
        } else if (u >= blo) {
            keep[i] = 0;
            int c = atomicAdd(&s_ncand, 1);
            if (c < MAXC) cand_idx[c] = i;
            else if (u >= thr) { keep[i] = 1; atomicAdd(&s_extra, 1); }
        } else {
            keep[i] = 0;
        }
    }
    if (my_above) atomicAdd(&s_above, my_above);
    __syncthreads();

    const int nc = (s_ncand < MAXC) ? s_ncand : MAXC;
    const int n_need = KSEL - s_above - s_extra;

    // Exact fp64 rescoring of the candidates.
    for (int c = 0; c < nc; c++) {
        const int o = cand_idx[c];
        const float* wr = Wr + (size_t)o * DDIM;
        double s = 0.0;
        for (int d = tid; d < DDIM; d += 256)
            s += (double)xrow[d] * (double)wr[d];
        red[tid] = s;
        __syncthreads();
        for (int off = 128; off > 0; off >>= 1) {
            if (tid < off) red[tid] += red[tid + off];
            __syncthreads();
        }
        if (tid == 0) cscore[c] = red[0] + (double)br[o];
        __syncthreads();
    }

    // Rank candidates by exact score; keep top n_need.
    if (tid < nc) {
        double mysc = cscore[tid];
        int rank = 0;
        for (int j = 0; j < nc; j++) {
            double sj = cscore[j];
            if (sj > mysc || (sj == mysc && j < tid)) rank++;
        }
        if (rank < n_need) keep[cand_idx[tid]] = 1;
    }
    __syncthreads();

    // Apply mask.
    for (int i = tid; i < ODIM; i += 256) {
        if (!keep[i]) out[base + i] = 0.0f;
    }
}

// ---------------------------------------------------------------------------
// Harness entry point. Device-global scratch never appears here.
// ---------------------------------------------------------------------------
extern "C" void kernel_launch(void* const* d_in, const int* in_sizes, int n_in,
                              void* d_out, int out_size)
{
    const float* x  = (const float*)d_in[0];
    const float* Wr = (const float*)d_in[1];
    const float* br = (const float*)d_in[2];
    const float* Wo = (const float*)d_in[3];
    const float* bo = (const float*)d_in[4];
    float* out = (float*)d_out;

    cudaFuncSetAttribute(gemm_mma3_kernel,
                         cudaFuncAttributeMaxDynamicSharedMemorySize, GSMEM);

    split_kernel<<<4096, 256>>>(x,  NTOK * DDIM / 4, 0);
    split_kernel<<<4096, 256>>>(Wr, ODIM * DDIM / 4, 1);
    split_kernel<<<4096, 256>>>(Wo, ODIM * DDIM / 4, 2);

    dim3 grid(ODIM / 128, NTOK / 128);
    gemm_mma3_kernel<<<grid, 256, GSMEM>>>(bo, out, 0);
    gemm_mma3_kernel<<<grid, 256, GSMEM>>>(br, out, 1);

    topk_fix_kernel<<<NTOK, 256>>>(x, Wr, br, out);
}

// round 12
// speedup vs baseline: 3.1722x; 1.7718x over previous
#include <cuda_runtime.h>
#include <cuda_fp16.h>
#include <cstdint>
#include <cstddef>

// Problem shape (fixed by the reference setup_inputs):
//   x: [8192, 4096] fp32, W_router/W_orig: [4096, 4096] fp32 (row-major, K contiguous)
//   out[n,o] = (x @ W_orig^T)[n,o] * topk_mask(x @ W_router^T)[n,o],  k = 1024 per row
#define NTOK 8192
#define DDIM 4096
#define ODIM 4096
#define KSEL 1024

// ---------------------------------------------------------------------------
// Device-global scratch (allocation-free rule). Referenced ONLY from device
// code — never passed as kernel arguments from host (shadow-address bug, R2-5).
// fp16 limb planes: hi = rn_fp16(x), lo = rn_fp16(x - hi). Pair error ~2^-22.
// ---------------------------------------------------------------------------
__device__ float  g_router[(size_t)NTOK * ODIM];
__device__ __half g_xh [(size_t)NTOK * DDIM];
__device__ __half g_xl [(size_t)NTOK * DDIM];
__device__ __half g_wrh[(size_t)ODIM * DDIM];
__device__ __half g_wrl[(size_t)ODIM * DDIM];
__device__ __half g_woh[(size_t)ODIM * DDIM];
__device__ __half g_wol[(size_t)ODIM * DDIM];

__device__ __forceinline__ uint32_t smem_u32(const void* p) {
    uint32_t a;
    asm("{ .reg .u64 t; cvta.to.shared.u64 t, %1; cvt.u32.u64 %0, t; }"
        : "=r"(a) : "l"(p));
    return a;
}

// Warp-level fp16 MMA, fp32 accumulate (base-arch, tensor pipe, 2x K of tf32):
// D(16x8,f32) += A(16x16,f16) * B(16x8,f16)
#define MMA_F16(c, a, b) \
    asm volatile( \
        "mma.sync.aligned.m16n8k16.row.col.f32.f16.f16.f32 " \
        "{%0,%1,%2,%3}, {%4,%5,%6,%7}, {%8,%9}, {%0,%1,%2,%3};" \
        : "+f"((c)[0]), "+f"((c)[1]), "+f"((c)[2]), "+f"((c)[3]) \
        : "r"((a)[0]), "r"((a)[1]), "r"((a)[2]), "r"((a)[3]), \
          "r"((b)[0]), "r"((b)[1]))

#define CP_ASYNC16(smem_u32_addr, gptr) \
    asm volatile("cp.async.cg.shared.global [%0], [%1], 16;" \
                 :: "r"(smem_u32_addr), "l"(gptr))
#define CP_COMMIT() asm volatile("cp.async.commit_group;" ::: "memory")
#define CP_WAIT1()  asm volatile("cp.async.wait_group 1;" ::: "memory")

// ---------------------------------------------------------------------------
// Split kernel: fp32 -> (fp16 hi, fp16 lo). x - hi is exact in fp32 (Dekker,
// round-to-nearest); lo captures bits 12-22 -> pair represents x to ~2^-22.
// which: 0 -> x, 1 -> W_router, 2 -> W_orig.
// ---------------------------------------------------------------------------
struct alignas(8) half4s { __half h[4]; };

__global__ __launch_bounds__(256)
void split_kernel(const float* __restrict__ src, int n4, int which)
{
    __half *hi, *lo;
    if (which == 0)      { hi = g_xh;  lo = g_xl;  }
    else if (which == 1) { hi = g_wrh; lo = g_wrl; }
    else                 { hi = g_woh; lo = g_wol; }

    const int stride = gridDim.x * blockDim.x;
    for (int i = blockIdx.x * blockDim.x + threadIdx.x; i < n4; i += stride) {
        float4 v = reinterpret_cast<const float4*>(src)[i];
        half4s H, L;
        H.h[0] = __float2half_rn(v.x);
        H.h[1] = __float2half_rn(v.y);
        H.h[2] = __float2half_rn(v.z);
        H.h[3] = __float2half_rn(v.w);
        L.h[0] = __float2half_rn(v.x - __half2float(H.h[0]));
        L.h[1] = __float2half_rn(v.y - __half2float(H.h[1]));
        L.h[2] = __float2half_rn(v.z - __half2float(H.h[2]));
        L.h[3] = __float2half_rn(v.w - __half2float(H.h[3]));
        reinterpret_cast<half4s*>(hi)[i] = H;
        reinterpret_cast<half4s*>(lo)[i] = L;
    }
}

// ---------------------------------------------------------------------------
// fp16x3 tensor-core GEMM (mma.sync m16n8k16), double-buffered cp.async.
// C = hiA*hiB + hiA*loB + loA*hiB  (+bias)   — tf32x3-grade accuracy at half
// the MMA instruction count and half the SMEM.
// which: 0 -> W_orig -> outp (d_out);  1 -> W_router -> g_router
// Block tile 128x128, BK=32, 256 threads = 8 warps (2 M x 4 N).
// PADH=40 halves/row: fragment u32 LDS banks = (20*row + tig) mod 32,
// all-distinct per warp -> conflict-free. 80 KB smem/CTA -> 2 CTAs/SM.
// ---------------------------------------------------------------------------
#define KITER  (DDIM / 32)
#define PADH   40                       // halves per padded row
#define TILEH  (128 * PADH)             // halves per tile
#define TILEB  (TILEH * 2)              // 10240 B
#define NTH    4                        // tiles per stage: Ahi,Alo,Bhi,Blo
#define STAGEH (NTH * TILEH)
#define GSMEM  (2 * NTH * TILEB)        // 81920 B

__global__ __launch_bounds__(256, 2)
void gemm_f16x3_kernel(const float* __restrict__ bias,
                       float* __restrict__ outp,
                       int which)
{
    extern __shared__ __half smh[];
    const int tid  = threadIdx.x;
    const int wid  = tid >> 5;
    const int lane = tid & 31;
    const int gid  = lane >> 2;
    const int tig  = lane & 3;

    const __half* __restrict__ Ah = g_xh;
    const __half* __restrict__ Al = g_xl;
    const __half* __restrict__ Bh = (which == 0) ? g_woh : g_wrh;
    const __half* __restrict__ Bl = (which == 0) ? g_wol : g_wrl;
    float* __restrict__ C = (which == 0) ? outp : g_router;

    const int mBase = blockIdx.y * 128;
    const int nBase = blockIdx.x * 128;
    const int warpM = (wid >> 2) * 64;
    const int warpN = (wid & 3) * 32;

    const uint32_t sb = smem_u32(smh);

    // slot: 0=Ahi 1=Alo 2=Bhi 3=Blo. Each tile: 128 rows x 32 halves (64B).
    auto load_tile = [&](int stage, int slot, const __half* __restrict__ g,
                         int rowBase, int k0) {
        const uint32_t dst = sb + (uint32_t)(stage * NTH + slot) * TILEB;
#pragma unroll
        for (int t = 0; t < 2; t++) {
            int idx = tid + t * 256;          // 0..511
            int row = idx >> 2;               // 0..127
            int c   = idx & 3;                // 16B chunk within 64B row
            const __half* src = g + (size_t)(rowBase + row) * DDIM + k0 + c * 8;
            uint32_t d = dst + (uint32_t)(row * (PADH * 2) + c * 16);
            CP_ASYNC16(d, src);
        }
    };
    auto load_stage = [&](int it, int stage) {
        const int k0 = it * 32;
        load_tile(stage, 0, Ah, mBase, k0);
        load_tile(stage, 1, Al, mBase, k0);
        load_tile(stage, 2, Bh, nBase, k0);
        load_tile(stage, 3, Bl, nBase, k0);
        CP_COMMIT();
    };

    float cfr[4][4][4];
#pragma unroll
    for (int mt = 0; mt < 4; mt++)
#pragma unroll
        for (int nt = 0; nt < 4; nt++)
#pragma unroll
            for (int q = 0; q < 4; q++) cfr[mt][nt][q] = 0.0f;

    load_stage(0, 0);
    load_stage(1, 1);

    for (int it = 0; it < KITER; it++) {
        CP_WAIT1();
        __syncthreads();

        const __half* Sa  = smh + (it & 1) * STAGEH;            // Ahi
        const __half* Sal = Sa + TILEH;                          // Alo
        const __half* Sb  = Sa + 2 * TILEH;                      // Bhi
        const __half* Sbl = Sa + 3 * TILEH;                      // Blo

#pragma unroll
        for (int ks = 0; ks < 2; ks++) {                         // k16 steps
            const int kh = ks * 16 + 2 * tig;
            uint32_t bh[4][2], bl[4][2];
#pragma unroll
            for (int nt = 0; nt < 4; nt++) {
                const int rn = (warpN + nt * 8 + gid) * PADH + kh;
                bh[nt][0] = *reinterpret_cast<const uint32_t*>(Sb  + rn);
                bh[nt][1] = *reinterpret_cast<const uint32_t*>(Sb  + rn + 8);
                bl[nt][0] = *reinterpret_cast<const uint32_t*>(Sbl + rn);
                bl[nt][1] = *reinterpret_cast<const uint32_t*>(Sbl + rn + 8);
            }
#pragma unroll
            for (int mt = 0; mt < 4; mt++) {
                const int r0 = (warpM + mt * 16 + gid) * PADH + kh;
                const int r1 = r0 + 8 * PADH;
                uint32_t ah[4], al[4];
                ah[0] = *reinterpret_cast<const uint32_t*>(Sa  + r0);
                ah[1] = *reinterpret_cast<const uint32_t*>(Sa  + r1);
                ah[2] = *reinterpret_cast<const uint32_t*>(Sa  + r0 + 8);
                ah[3] = *reinterpret_cast<const uint32_t*>(Sa  + r1 + 8);
                al[0] = *reinterpret_cast<const uint32_t*>(Sal + r0);
                al[1] = *reinterpret_cast<const uint32_t*>(Sal + r1);
                al[2] = *reinterpret_cast<const uint32_t*>(Sal + r0 + 8);
                al[3] = *reinterpret_cast<const uint32_t*>(Sal + r1 + 8);
#pragma unroll
                for (int nt = 0; nt < 4; nt++) {
                    MMA_F16(cfr[mt][nt], ah, bh[nt]);
                    MMA_F16(cfr[mt][nt], ah, bl[nt]);
                    MMA_F16(cfr[mt][nt], al, bh[nt]);
                }
            }
        }
        __syncthreads();
        if (it + 2 < KITER) load_stage(it + 2, it & 1);
    }

    // Epilogue: c0,c1 -> (row, col..col+1); c2,c3 -> (row+8, col..col+1)
#pragma unroll
    for (int mt = 0; mt < 4; mt++) {
        const int row = mBase + warpM + mt * 16 + gid;
#pragma unroll
        for (int nt = 0; nt < 4; nt++) {
            const int col = nBase + warpN + nt * 8 + tig * 2;
            const float b0 = bias[col], b1 = bias[col + 1];
            float2 v0 = make_float2(cfr[mt][nt][0] + b0, cfr[mt][nt][1] + b1);
            float2 v1 = make_float2(cfr[mt][nt][2] + b0, cfr[mt][nt][3] + b1);
            *reinterpret_cast<float2*>(&C[(size_t)row * ODIM + col]) = v0;
            *reinterpret_cast<float2*>(&C[(size_t)(row + 8) * ODIM + col]) = v1;
        }
    }
}

// ---------------------------------------------------------------------------
// Top-k with exact boundary fixup (unchanged from the R10 passing run).
//  1. radix-select approx threshold on g_router logits
//  2. logits within +-DELTA of it rescored EXACTLY (fp64 dot of x.Wr+br)
//  3. keep = above band  U  exact-top of band (exactly KSEL kept)
// fp16x3 router noise ~1e-5 -> DELTA = 4e-3 is a ~400-sigma band.
// ---------------------------------------------------------------------------
#define DELTA 4e-3f
#define MAXC  128

__device__ __forceinline__ unsigned int f2ord(float f) {
    unsigned int b = __float_as_uint(f);
    return (b & 0x80000000u) ? ~b : (b | 0x80000000u);
}

__global__ __launch_bounds__(256)
void topk_fix_kernel(const float* __restrict__ x,
                     const float* __restrict__ Wr,
                     const float* __restrict__ br,
                     float* __restrict__ out)
{
    __shared__ float xrow[DDIM];
    __shared__ unsigned int srow[ODIM];
    __shared__ unsigned char keep[ODIM];
    __shared__ unsigned int hist[256];
    __shared__ int cand_idx[MAXC];
    __shared__ double cscore[MAXC];
    __shared__ double red[256];
    __shared__ unsigned int s_prefix;
    __shared__ int s_kk, s_ncand, s_above, s_extra;
    __shared__ unsigned int s_bhi, s_blo;

    const int row = blockIdx.x;
    const int tid = threadIdx.x;
    const size_t base = (size_t)row * ODIM;

    for (int i = tid; i < DDIM; i += 256)
        xrow[i] = x[(size_t)row * DDIM + i];
    for (int i = tid; i < ODIM; i += 256)
        srow[i] = f2ord(g_router[base + i]);

    if (tid == 0) {
        s_prefix = 0u; s_kk = KSEL;
        s_ncand = 0; s_above = 0; s_extra = 0;
    }
    __syncthreads();

    for (int shift = 24; shift >= 0; shift -= 8) {
        hist[tid] = 0u;
        __syncthreads();
        const unsigned int prefix = s_prefix;
        const unsigned int maskhi = (shift == 24) ? 0u
                                                  : (0xFFFFFFFFu << (shift + 8));
        for (int i = tid; i < ODIM; i += 256) {
            unsigned int u = srow[i];
            if ((u & maskhi) == prefix)
                atomicAdd(&hist[(u >> shift) & 0xFFu], 1u);
        }
        __syncthreads();
        if (tid == 0) {
            int kk = s_kk, cum = 0, b = 255;
            for (; b >= 0; b--) {
                cum += (int)hist[b];
                if (cum >= kk) break;
            }
            s_kk = kk - (cum - (int)hist[b]);
            s_prefix = prefix | ((unsigned int)b << shift);
        }
        __syncthreads();
    }

    const unsigned int thr = s_prefix;
    if (tid == 0) {
        unsigned int b = (thr & 0x80000000u) ? (thr & 0x7FFFFFFFu) : ~thr;
        float vthr = __uint_as_float(b);
        s_bhi = f2ord(vthr + DELTA);
        s_blo = f2ord(vthr - DELTA);
    }
    __syncthreads();
    const unsigned int bhi = s_bhi, blo = s_blo;

    int my_above = 0;
    for (int i = tid; i < ODIM; i += 256) {
        unsigned int u = srow[i];
        if (u > bhi) {
            keep[i] = 1; my_above++;
        } else if (u >= blo) {
            keep[i] = 0;
            int c = atomicAdd(&s_ncand, 1);
            if (c < MAXC) cand_idx[c] = i;
            else if (u >= thr) { keep[i] = 1; atomicAdd(&s_extra, 1); }
        } else {
            keep[i] = 0;
        }
    }
    if (my_above) atomicAdd(&s_above, my_above);
    __syncthreads();

    const int nc = (s_ncand < MAXC) ? s_ncand : MAXC;
    const int n_need = KSEL - s_above - s_extra;

    for (int c = 0; c < nc; c++) {
        const int o = cand_idx[c];
        const float* wr = Wr + (size_t)o * DDIM;
        double s = 0.0;
        for (int d = tid; d < DDIM; d += 256)
            s += (double)xrow[d] * (double)wr[d];
        red[tid] = s;
        __syncthreads();
        for (int off = 128; off > 0; off >>= 1) {
            if (tid < off) red[tid] += red[tid + off];
            __syncthreads();
        }
        if (tid == 0) cscore[c] = red[0] + (double)br[o];
        __syncthreads();
    }

    if (tid < nc) {
        double mysc = cscore[tid];
        int rank = 0;
        for (int j = 0; j < nc; j++) {
            double sj = cscore[j];
            if (sj > mysc || (sj == mysc && j < tid)) rank++;
        }
        if (rank < n_need) keep[cand_idx[tid]] = 1;
    }
    __syncthreads();

    for (int i = tid; i < ODIM; i += 256) {
        if (!keep[i]) out[base + i] = 0.0f;
    }
}

// ---------------------------------------------------------------------------
// Harness entry point. Device-global scratch never appears here.
// ---------------------------------------------------------------------------
extern "C" void kernel_launch(void* const* d_in, const int* in_sizes, int n_in,
                              void* d_out, int out_size)
{
    const float* x  = (const float*)d_in[0];
    const float* Wr = (const float*)d_in[1];
    const float* br = (const float*)d_in[2];
    const float* Wo = (const float*)d_in[3];
    const float* bo = (const float*)d_in[4];
    float* out = (float*)d_out;

    cudaFuncSetAttribute(gemm_f16x3_kernel,
                         cudaFuncAttributeMaxDynamicSharedMemorySize, GSMEM);

    split_kernel<<<4096, 256>>>(x,  NTOK * DDIM / 4, 0);
    split_kernel<<<4096, 256>>>(Wr, ODIM * DDIM / 4, 1);
    split_kernel<<<4096, 256>>>(Wo, ODIM * DDIM / 4, 2);

    dim3 grid(ODIM / 128, NTOK / 128);
    gemm_f16x3_kernel<<<grid, 256, GSMEM>>>(bo, out, 0);
    gemm_f16x3_kernel<<<grid, 256, GSMEM>>>(br, out, 1);

    topk_fix_kernel<<<NTOK, 256>>>(x, Wr, br, out);
}

// round 13
// speedup vs baseline: 3.5181x; 1.1090x over previous
#include <cuda_runtime.h>
#include <cuda_fp16.h>
#include <cstdint>
#include <cstddef>

// Problem shape (fixed by the reference setup_inputs):
//   x: [8192, 4096] fp32, W_router/W_orig: [4096, 4096] fp32 (row-major, K contiguous)
//   out[n,o] = (x @ W_orig^T)[n,o] * topk_mask(x @ W_router^T)[n,o],  k = 1024 per row
#define NTOK 8192
#define DDIM 4096
#define ODIM 4096
#define KSEL 1024

// ---------------------------------------------------------------------------
// Device-global scratch (allocation-free rule). Referenced ONLY from device
// code — never passed as kernel arguments from host (shadow-address bug, R2-5).
// fp16 limb planes: hi = rn_fp16(x), lo = rn_fp16(x - hi). Pair error ~2^-22.
// ---------------------------------------------------------------------------
__device__ float  g_router[(size_t)NTOK * ODIM];
__device__ __half g_xh [(size_t)NTOK * DDIM];
__device__ __half g_xl [(size_t)NTOK * DDIM];
__device__ __half g_wrh[(size_t)ODIM * DDIM];
__device__ __half g_wrl[(size_t)ODIM * DDIM];
__device__ __half g_woh[(size_t)ODIM * DDIM];
__device__ __half g_wol[(size_t)ODIM * DDIM];

__device__ __forceinline__ uint32_t smem_u32(const void* p) {
    uint32_t a;
    asm("{ .reg .u64 t; cvta.to.shared.u64 t, %1; cvt.u32.u64 %0, t; }"
        : "=r"(a) : "l"(p));
    return a;
}

// Warp-level fp16 MMA, fp32 accumulate:
// D(16x8,f32) += A(16x16,f16) * B(16x8,f16)
#define MMA_F16(c, a, b) \
    asm volatile( \
        "mma.sync.aligned.m16n8k16.row.col.f32.f16.f16.f32 " \
        "{%0,%1,%2,%3}, {%4,%5,%6,%7}, {%8,%9}, {%0,%1,%2,%3};" \
        : "+f"((c)[0]), "+f"((c)[1]), "+f"((c)[2]), "+f"((c)[3]) \
        : "r"((a)[0]), "r"((a)[1]), "r"((a)[2]), "r"((a)[3]), \
          "r"((b)[0]), "r"((b)[1]))

// 4-matrix ldmatrix: 4 fragment regs per instruction, per-lane row address.
#define LDMX4(r0, r1, r2, r3, addr) \
    asm volatile("ldmatrix.sync.aligned.m8n8.x4.shared.b16 {%0,%1,%2,%3}, [%4];" \
        : "=r"(r0), "=r"(r1), "=r"(r2), "=r"(r3) : "r"(addr))

#define CP_ASYNC16(smem_u32_addr, gptr) \
    asm volatile("cp.async.cg.shared.global [%0], [%1], 16;" \
                 :: "r"(smem_u32_addr), "l"(gptr))
#define CP_COMMIT() asm volatile("cp.async.commit_group;" ::: "memory")
#define CP_WAIT1()  asm volatile("cp.async.wait_group 1;" ::: "memory")

// ---------------------------------------------------------------------------
// Split kernel: fp32 -> (fp16 hi, fp16 lo) Dekker split.
// which: 0 -> x, 1 -> W_router, 2 -> W_orig.
// ---------------------------------------------------------------------------
struct alignas(8) half4s { __half h[4]; };

__global__ __launch_bounds__(256)
void split_kernel(const float* __restrict__ src, int n4, int which)
{
    __half *hi, *lo;
    if (which == 0)      { hi = g_xh;  lo = g_xl;  }
    else if (which == 1) { hi = g_wrh; lo = g_wrl; }
    else                 { hi = g_woh; lo = g_wol; }

    const int stride = gridDim.x * blockDim.x;
    for (int i = blockIdx.x * blockDim.x + threadIdx.x; i < n4; i += stride) {
        float4 v = reinterpret_cast<const float4*>(src)[i];
        half4s H, L;
        H.h[0] = __float2half_rn(v.x);
        H.h[1] = __float2half_rn(v.y);
        H.h[2] = __float2half_rn(v.z);
        H.h[3] = __float2half_rn(v.w);
        L.h[0] = __float2half_rn(v.x - __half2float(H.h[0]));
        L.h[1] = __float2half_rn(v.y - __half2float(H.h[1]));
        L.h[2] = __float2half_rn(v.z - __half2float(H.h[2]));
        L.h[3] = __float2half_rn(v.w - __half2float(H.h[3]));
        reinterpret_cast<half4s*>(hi)[i] = H;
        reinterpret_cast<half4s*>(lo)[i] = L;
    }
}

// ---------------------------------------------------------------------------
// fp16x3 tensor-core GEMM (mma.sync m16n8k16), double-buffered cp.async,
// ldmatrix.x4 fragment loads (24 ldmatrix/warp-iter vs 96 scalar LDS).
// C = hiA*hiB + hiA*loB + loA*hiB (+bias).
// which: 0 -> W_orig -> outp (d_out);  1 -> W_router -> g_router
// Block tile 128x128, BK=32, 256 threads = 8 warps (2 M x 4 N).
// PADH=40: ldmatrix row stride 80 B -> bank-group 5r mod 8, conflict-free.
// 80 KB smem/CTA -> 2 CTAs/SM.
// ---------------------------------------------------------------------------
#define KITER  (DDIM / 32)
#define PADH   40                       // halves per padded row
#define ROWB   (PADH * 2)               // 80 bytes per row
#define TILEH  (128 * PADH)
#define TILEB  (TILEH * 2)              // 10240 B
#define NTH    4                        // tiles per stage: Ahi,Alo,Bhi,Blo
#define STAGEB (NTH * TILEB)
#define GSMEM  (2 * STAGEB)             // 81920 B

__global__ __launch_bounds__(256, 2)
void gemm_f16x3_kernel(const float* __restrict__ bias,
                       float* __restrict__ outp,
                       int which)
{
    extern __shared__ __half smh[];
    const int tid  = threadIdx.x;
    const int wid  = tid >> 5;
    const int lane = tid & 31;
    const int gid  = lane >> 2;
    const int tig  = lane & 3;

    const __half* __restrict__ Ah = g_xh;
    const __half* __restrict__ Al = g_xl;
    const __half* __restrict__ Bh = (which == 0) ? g_woh : g_wrh;
    const __half* __restrict__ Bl = (which == 0) ? g_wol : g_wrl;
    float* __restrict__ C = (which == 0) ? outp : g_router;

    const int mBase = blockIdx.y * 128;
    const int nBase = blockIdx.x * 128;
    const int warpM = (wid >> 2) * 64;
    const int warpN = (wid & 3) * 32;

    const uint32_t sb = smem_u32(smh);

    // ldmatrix per-lane address components (j = lane/8 selects the matrix)
    const int lj = lane >> 3;
    const int lr = lane & 7;
    // A x4 matrices: (rows 0-7,k0),(rows 8-15,k0),(rows 0-7,k0+8),(rows 8-15,k0+8)
    //   -> regs a0,a1,a2,a3 per PTX m16n8k16 fragment layout
    const uint32_t aAddrBase =
        (uint32_t)((warpM + ((lj & 1) << 3) + lr) * ROWB + ((lj >> 1) << 4));
    // B x4 matrices: (nt0,k0),(nt0,k0+8),(nt1,k0),(nt1,k0+8) for an nt-pair
    const uint32_t bAddrBase =
        (uint32_t)((warpN + ((lj >> 1) << 3) + lr) * ROWB + ((lj & 1) << 4));

    // slot: 0=Ahi 1=Alo 2=Bhi 3=Blo. Each tile row: 32 halves (64B) loaded.
    auto load_tile = [&](int stage, int slot, const __half* __restrict__ g,
                         int rowBase, int k0) {
        const uint32_t dst = sb + (uint32_t)(stage * NTH + slot) * TILEB;
#pragma unroll
        for (int t = 0; t < 2; t++) {
            int idx = tid + t * 256;          // 0..511
            int row = idx >> 2;               // 0..127
            int c   = idx & 3;                // 16B chunk within 64B row
            const __half* src = g + (size_t)(rowBase + row) * DDIM + k0 + c * 8;
            uint32_t d = dst + (uint32_t)(row * ROWB + c * 16);
            CP_ASYNC16(d, src);
        }
    };
    auto load_stage = [&](int it, int stage) {
        const int k0 = it * 32;
        load_tile(stage, 0, Ah, mBase, k0);
        load_tile(stage, 1, Al, mBase, k0);
        load_tile(stage, 2, Bh, nBase, k0);
        load_tile(stage, 3, Bl, nBase, k0);
        CP_COMMIT();
    };

    float cfr[4][4][4];
#pragma unroll
    for (int mt = 0; mt < 4; mt++)
#pragma unroll
        for (int nt = 0; nt < 4; nt++)
#pragma unroll
            for (int q = 0; q < 4; q++) cfr[mt][nt][q] = 0.0f;

    load_stage(0, 0);
    load_stage(1, 1);

    for (int it = 0; it < KITER; it++) {
        CP_WAIT1();
        __syncthreads();

        const uint32_t stg = sb + (uint32_t)(it & 1) * STAGEB;
        const uint32_t tAh = stg;                 // Ahi tile base
        const uint32_t tAl = stg + TILEB;         // Alo
        const uint32_t tBh = stg + 2 * TILEB;     // Bhi
        const uint32_t tBl = stg + 3 * TILEB;     // Blo

#pragma unroll
        for (int ks = 0; ks < 2; ks++) {          // k16 steps (ks*32 bytes)
            const uint32_t kOff = (uint32_t)(ks << 5);
            uint32_t bh[4][2], bl[4][2];
#pragma unroll
            for (int p = 0; p < 2; p++) {         // nt pairs (0,1) and (2,3)
                const uint32_t bo = bAddrBase + (uint32_t)(p * 16 * ROWB) + kOff;
                LDMX4(bh[2*p][0], bh[2*p][1], bh[2*p+1][0], bh[2*p+1][1], tBh + bo);
                LDMX4(bl[2*p][0], bl[2*p][1], bl[2*p+1][0], bl[2*p+1][1], tBl + bo);
            }
#pragma unroll
            for (int mt = 0; mt < 4; mt++) {
                const uint32_t ao = aAddrBase + (uint32_t)(mt * 16 * ROWB) + kOff;
                uint32_t ah[4], al[4];
                LDMX4(ah[0], ah[1], ah[2], ah[3], tAh + ao);
                LDMX4(al[0], al[1], al[2], al[3], tAl + ao);
#pragma unroll
                for (int nt = 0; nt < 4; nt++) {
                    MMA_F16(cfr[mt][nt], ah, bh[nt]);
                    MMA_F16(cfr[mt][nt], ah, bl[nt]);
                    MMA_F16(cfr[mt][nt], al, bh[nt]);
                }
            }
        }
        __syncthreads();
        if (it + 2 < KITER) load_stage(it + 2, it & 1);
    }

    // Epilogue: c0,c1 -> (row, col..col+1); c2,c3 -> (row+8, col..col+1)
#pragma unroll
    for (int mt = 0; mt < 4; mt++) {
        const int row = mBase + warpM + mt * 16 + gid;
#pragma unroll
        for (int nt = 0; nt < 4; nt++) {
            const int col = nBase + warpN + nt * 8 + tig * 2;
            const float b0 = bias[col], b1 = bias[col + 1];
            float2 v0 = make_float2(cfr[mt][nt][0] + b0, cfr[mt][nt][1] + b1);
            float2 v1 = make_float2(cfr[mt][nt][2] + b0, cfr[mt][nt][3] + b1);
            *reinterpret_cast<float2*>(&C[(size_t)row * ODIM + col]) = v0;
            *reinterpret_cast<float2*>(&C[(size_t)(row + 8) * ODIM + col]) = v1;
        }
    }
}

// ---------------------------------------------------------------------------
// Top-k with exact boundary fixup. One block per row.
//  1. radix-select approx threshold on g_router logits
//  2. logits within +-DELTA rescored EXACTLY (fp64 dot), warp-per-candidate
//  3. keep = above band  U  exact-top of band (exactly KSEL kept)
// fp16x3 router noise ~1.4e-5 -> DELTA = 5e-4 is a ~35-sigma band
// (safe even at the 5x empirical fudge factor), ~1.3 candidates/row.
// ---------------------------------------------------------------------------
#define DELTA 5e-4f
#define MAXC  128

__device__ __forceinline__ unsigned int f2ord(float f) {
    unsigned int b = __float_as_uint(f);
    return (b & 0x80000000u) ? ~b : (b | 0x80000000u);
}

__global__ __launch_bounds__(256)
void topk_fix_kernel(const float* __restrict__ x,
                     const float* __restrict__ Wr,
                     const float* __restrict__ br,
                     float* __restrict__ out)
{
    __shared__ float xrow[DDIM];
    __shared__ unsigned int srow[ODIM];
    __shared__ unsigned char keep[ODIM];
    __shared__ unsigned int hist[256];
    __shared__ int cand_idx[MAXC];
    __shared__ double cscore[MAXC];
    __shared__ unsigned int s_prefix;
    __shared__ int s_kk, s_ncand, s_above, s_extra;
    __shared__ unsigned int s_bhi, s_blo;

    const int row = blockIdx.x;
    const int tid = threadIdx.x;
    const int wid = tid >> 5;
    const int lane = tid & 31;
    const size_t base = (size_t)row * ODIM;

    for (int i = tid; i < DDIM; i += 256)
        xrow[i] = x[(size_t)row * DDIM + i];
    for (int i = tid; i < ODIM; i += 256)
        srow[i] = f2ord(g_router[base + i]);

    if (tid == 0) {
        s_prefix = 0u; s_kk = KSEL;
        s_ncand = 0; s_above = 0; s_extra = 0;
    }
    __syncthreads();

    for (int shift = 24; shift >= 0; shift -= 8) {
        hist[tid] = 0u;
        __syncthreads();
        const unsigned int prefix = s_prefix;
        const unsigned int maskhi = (shift == 24) ? 0u
                                                  : (0xFFFFFFFFu << (shift + 8));
        for (int i = tid; i < ODIM; i += 256) {
            unsigned int u = srow[i];
            if ((u & maskhi) == prefix)
                atomicAdd(&hist[(u >> shift) & 0xFFu], 1u);
        }
        __syncthreads();
        if (tid == 0) {
            int kk = s_kk, cum = 0, b = 255;
            for (; b >= 0; b--) {
                cum += (int)hist[b];
                if (cum >= kk) break;
            }
            s_kk = kk - (cum - (int)hist[b]);
            s_prefix = prefix | ((unsigned int)b << shift);
        }
        __syncthreads();
    }

    const unsigned int thr = s_prefix;
    if (tid == 0) {
        unsigned int b = (thr & 0x80000000u) ? (thr & 0x7FFFFFFFu) : ~thr;
        float vthr = __uint_as_float(b);
        s_bhi = f2ord(vthr + DELTA);
        s_blo = f2ord(vthr - DELTA);
    }
    __syncthreads();
    const unsigned int bhi = s_bhi, blo = s_blo;

    int my_above = 0;
    for (int i = tid; i < ODIM; i += 256) {
        unsigned int u = srow[i];
        if (u > bhi) {
            keep[i] = 1; my_above++;
        } else if (u >= blo) {
            keep[i] = 0;
            int c = atomicAdd(&s_ncand, 1);
            if (c < MAXC) cand_idx[c] = i;
            else if (u >= thr) { keep[i] = 1; atomicAdd(&s_extra, 1); }
        } else {
            keep[i] = 0;
        }
    }
    if (my_above) atomicAdd(&s_above, my_above);
    __syncthreads();

    const int nc = (s_ncand < MAXC) ? s_ncand : MAXC;
    const int n_need = KSEL - s_above - s_extra;

    // Exact fp64 rescoring: one warp per candidate, shfl reduction.
    for (int c = wid; c < nc; c += 8) {
        const int o = cand_idx[c];
        const float* wr = Wr + (size_t)o * DDIM;
        double s = 0.0;
        for (int d = lane; d < DDIM; d += 32)
            s += (double)xrow[d] * (double)wr[d];
#pragma unroll
        for (int off = 16; off > 0; off >>= 1)
            s += __shfl_down_sync(0xFFFFFFFFu, s, off);
        if (lane == 0) cscore[c] = s + (double)br[o];
    }
    __syncthreads();

    if (tid < nc) {
        double mysc = cscore[tid];
        int rank = 0;
        for (int j = 0; j < nc; j++) {
            double sj = cscore[j];
            if (sj > mysc || (sj == mysc && j < tid)) rank++;
        }
        if (rank < n_need) keep[cand_idx[tid]] = 1;
    }
    __syncthreads();

    for (int i = tid; i < ODIM; i += 256) {
        if (!keep[i]) out[base + i] = 0.0f;
    }
}

// ---------------------------------------------------------------------------
// Harness entry point. Device-global scratch never appears here.
// ---------------------------------------------------------------------------
extern "C" void kernel_launch(void* const* d_in, const int* in_sizes, int n_in,
                              void* d_out, int out_size)
{
    const float* x  = (const float*)d_in[0];
    const float* Wr = (const float*)d_in[1];
    const float* br = (const float*)d_in[2];
    const float* Wo = (const float*)d_in[3];
    const float* bo = (const float*)d_in[4];
    float* out = (float*)d_out;

    cudaFuncSetAttribute(gemm_f16x3_kernel,
                         cudaFuncAttributeMaxDynamicSharedMemorySize, GSMEM);

    split_kernel<<<4096, 256>>>(x,  NTOK * DDIM / 4, 0);
    split_kernel<<<4096, 256>>>(Wr, ODIM * DDIM / 4, 1);
    split_kernel<<<4096, 256>>>(Wo, ODIM * DDIM / 4, 2);

    dim3 grid(ODIM / 128, NTOK / 128);
    gemm_f16x3_kernel<<<grid, 256, GSMEM>>>(bo, out, 0);
    gemm_f16x3_kernel<<<grid, 256, GSMEM>>>(br, out, 1);

    topk_fix_kernel<<<NTOK, 256>>>(x, Wr, br, out);
}

// round 14
// speedup vs baseline: 4.8914x; 1.3904x over previous
#include <cuda_runtime.h>
#include <cuda_fp16.h>
#include <cstdint>
#include <cstddef>

// Problem shape (fixed by the reference setup_inputs):
//   x: [8192, 4096] fp32, W_router/W_orig: [4096, 4096] fp32 (row-major, K contiguous)
//   out[n,o] = (x @ W_orig^T)[n,o] * topk_mask(x @ W_router^T)[n,o],  k = 1024 per row
#define NTOK 8192
#define DDIM 4096
#define ODIM 4096
#define KSEL 1024

// ---------------------------------------------------------------------------
// Device-global scratch (allocation-free rule). Referenced ONLY from device
// code — never passed as kernel arguments from host (shadow-address bug, R2-5).
// fp16x2 GEMM: C = hiA*(hiB+loB) = hiA*B_exact; only error is the dropped
// loA*B term (logit sigma ~1.4e-4, deterministic — no accumulation fudge).
// x needs only its hi limb; W needs hi+lo.
// ---------------------------------------------------------------------------
__device__ float  g_router[(size_t)NTOK * ODIM];
__device__ __half g_xh [(size_t)NTOK * DDIM];
__device__ __half g_wrh[(size_t)ODIM * DDIM];
__device__ __half g_wrl[(size_t)ODIM * DDIM];
__device__ __half g_woh[(size_t)ODIM * DDIM];
__device__ __half g_wol[(size_t)ODIM * DDIM];

__device__ __forceinline__ uint32_t smem_u32(const void* p) {
    uint32_t a;
    asm("{ .reg .u64 t; cvta.to.shared.u64 t, %1; cvt.u32.u64 %0, t; }"
        : "=r"(a) : "l"(p));
    return a;
}

// Warp-level fp16 MMA, fp32 accumulate:
// D(16x8,f32) += A(16x16,f16) * B(16x8,f16)
#define MMA_F16(c, a, b) \
    asm volatile( \
        "mma.sync.aligned.m16n8k16.row.col.f32.f16.f16.f32 " \
        "{%0,%1,%2,%3}, {%4,%5,%6,%7}, {%8,%9}, {%0,%1,%2,%3};" \
        : "+f"((c)[0]), "+f"((c)[1]), "+f"((c)[2]), "+f"((c)[3]) \
        : "r"((a)[0]), "r"((a)[1]), "r"((a)[2]), "r"((a)[3]), \
          "r"((b)[0]), "r"((b)[1]))

// 4-matrix ldmatrix: 4 fragment regs per instruction, per-lane row address.
#define LDMX4(r0, r1, r2, r3, addr) \
    asm volatile("ldmatrix.sync.aligned.m8n8.x4.shared.b16 {%0,%1,%2,%3}, [%4];" \
        : "=r"(r0), "=r"(r1), "=r"(r2), "=r"(r3) : "r"(addr))

#define CP_ASYNC16(smem_u32_addr, gptr) \
    asm volatile("cp.async.cg.shared.global [%0], [%1], 16;" \
                 :: "r"(smem_u32_addr), "l"(gptr))
#define CP_COMMIT() asm volatile("cp.async.commit_group;" ::: "memory")
#define CP_WAIT1()  asm volatile("cp.async.wait_group 1;" ::: "memory")

// ---------------------------------------------------------------------------
// Split kernels. Dekker: hi = rn16(v), lo = rn16(v - hi) (v - hi exact fp32).
// ---------------------------------------------------------------------------
struct alignas(8) half4s { __half h[4]; };

// hi-only split for x
__global__ __launch_bounds__(256)
void split_hi_kernel(const float* __restrict__ src, int n4)
{
    __half* hi = g_xh;
    const int stride = gridDim.x * blockDim.x;
    for (int i = blockIdx.x * blockDim.x + threadIdx.x; i < n4; i += stride) {
        float4 v = reinterpret_cast<const float4*>(src)[i];
        half4s H;
        H.h[0] = __float2half_rn(v.x);
        H.h[1] = __float2half_rn(v.y);
        H.h[2] = __float2half_rn(v.z);
        H.h[3] = __float2half_rn(v.w);
        reinterpret_cast<half4s*>(hi)[i] = H;
    }
}

// hi+lo split for weights. which: 1 -> W_router, 2 -> W_orig.
__global__ __launch_bounds__(256)
void split_hl_kernel(const float* __restrict__ src, int n4, int which)
{
    __half *hi, *lo;
    if (which == 1) { hi = g_wrh; lo = g_wrl; }
    else            { hi = g_woh; lo = g_wol; }

    const int stride = gridDim.x * blockDim.x;
    for (int i = blockIdx.x * blockDim.x + threadIdx.x; i < n4; i += stride) {
        float4 v = reinterpret_cast<const float4*>(src)[i];
        half4s H, L;
        H.h[0] = __float2half_rn(v.x);
        H.h[1] = __float2half_rn(v.y);
        H.h[2] = __float2half_rn(v.z);
        H.h[3] = __float2half_rn(v.w);
        L.h[0] = __float2half_rn(v.x - __half2float(H.h[0]));
        L.h[1] = __float2half_rn(v.y - __half2float(H.h[1]));
        L.h[2] = __float2half_rn(v.z - __half2float(H.h[2]));
        L.h[3] = __float2half_rn(v.w - __half2float(H.h[3]));
        reinterpret_cast<half4s*>(hi)[i] = H;
        reinterpret_cast<half4s*>(lo)[i] = L;
    }
}

// ---------------------------------------------------------------------------
// fp16x2 tensor-core GEMM (mma.sync m16n8k16), double-buffered cp.async,
// ldmatrix.x4 fragment loads. C = hiA*hiB + hiA*loB (+bias) = hiA*B + bias.
// which: 0 -> W_orig -> outp (d_out);  1 -> W_router -> g_router
// Block tile 128x128, BK=32, 256 threads = 8 warps (2 M x 4 N).
// PADH=40: ldmatrix row stride 80 B -> conflict-free (proven R12/13).
// 60 KB smem/CTA -> 2 CTAs/SM.
// ---------------------------------------------------------------------------
#define KITER  (DDIM / 32)
#define PADH   40                       // halves per padded row
#define ROWB   (PADH * 2)               // 80 bytes per row
#define TILEH  (128 * PADH)
#define TILEB  (TILEH * 2)              // 10240 B
#define NTH    3                        // tiles per stage: Ah, Bh, Bl
#define STAGEB (NTH * TILEB)
#define GSMEM  (2 * STAGEB)             // 61440 B

__global__ __launch_bounds__(256, 2)
void gemm_f16x2_kernel(const float* __restrict__ bias,
                       float* __restrict__ outp,
                       int which)
{
    extern __shared__ __half smh[];
    const int tid  = threadIdx.x;
    const int wid  = tid >> 5;
    const int lane = tid & 31;
    const int gid  = lane >> 2;
    const int tig  = lane & 3;

    const __half* __restrict__ Ah = g_xh;
    const __half* __restrict__ Bh = (which == 0) ? g_woh : g_wrh;
    const __half* __restrict__ Bl = (which == 0) ? g_wol : g_wrl;
    float* __restrict__ C = (which == 0) ? outp : g_router;

    const int mBase = blockIdx.y * 128;
    const int nBase = blockIdx.x * 128;
    const int warpM = (wid >> 2) * 64;
    const int warpN = (wid & 3) * 32;

    const uint32_t sb = smem_u32(smh);

    // ldmatrix per-lane address components (j = lane/8 selects the matrix)
    const int lj = lane >> 3;
    const int lr = lane & 7;
    // A x4: (rows 0-7,k0),(rows 8-15,k0),(rows 0-7,k0+8),(rows 8-15,k0+8)
    const uint32_t aAddrBase =
        (uint32_t)((warpM + ((lj & 1) << 3) + lr) * ROWB + ((lj >> 1) << 4));
    // B x4: (nt0,k0),(nt0,k0+8),(nt1,k0),(nt1,k0+8) for an nt-pair
    const uint32_t bAddrBase =
        (uint32_t)((warpN + ((lj >> 1) << 3) + lr) * ROWB + ((lj & 1) << 4));

    // slot: 0=Ah 1=Bh 2=Bl. Each tile row: 32 halves (64B) loaded.
    auto load_tile = [&](int stage, int slot, const __half* __restrict__ g,
                         int rowBase, int k0) {
        const uint32_t dst = sb + (uint32_t)(stage * NTH + slot) * TILEB;
#pragma unroll
        for (int t = 0; t < 2; t++) {
            int idx = tid + t * 256;          // 0..511
            int row = idx >> 2;               // 0..127
            int c   = idx & 3;                // 16B chunk within 64B row
            const __half* src = g + (size_t)(rowBase + row) * DDIM + k0 + c * 8;
            uint32_t d = dst + (uint32_t)(row * ROWB + c * 16);
            CP_ASYNC16(d, src);
        }
    };
    auto load_stage = [&](int it, int stage) {
        const int k0 = it * 32;
        load_tile(stage, 0, Ah, mBase, k0);
        load_tile(stage, 1, Bh, nBase, k0);
        load_tile(stage, 2, Bl, nBase, k0);
        CP_COMMIT();
    };

    float cfr[4][4][4];
#pragma unroll
    for (int mt = 0; mt < 4; mt++)
#pragma unroll
        for (int nt = 0; nt < 4; nt++)
#pragma unroll
            for (int q = 0; q < 4; q++) cfr[mt][nt][q] = 0.0f;

    load_stage(0, 0);
    load_stage(1, 1);

    for (int it = 0; it < KITER; it++) {
        CP_WAIT1();
        __syncthreads();

        const uint32_t stg = sb + (uint32_t)(it & 1) * STAGEB;
        const uint32_t tAh = stg;                 // Ah tile base
        const uint32_t tBh = stg + TILEB;         // Bh
        const uint32_t tBl = stg + 2 * TILEB;     // Bl

#pragma unroll
        for (int ks = 0; ks < 2; ks++) {          // k16 steps (ks*32 bytes)
            const uint32_t kOff = (uint32_t)(ks << 5);
            uint32_t bh[4][2], bl[4][2];
#pragma unroll
            for (int p = 0; p < 2; p++) {         // nt pairs (0,1) and (2,3)
                const uint32_t bo = bAddrBase + (uint32_t)(p * 16 * ROWB) + kOff;
                LDMX4(bh[2*p][0], bh[2*p][1], bh[2*p+1][0], bh[2*p+1][1], tBh + bo);
                LDMX4(bl[2*p][0], bl[2*p][1], bl[2*p+1][0], bl[2*p+1][1], tBl + bo);
            }
#pragma unroll
            for (int mt = 0; mt < 4; mt++) {
                const uint32_t ao = aAddrBase + (uint32_t)(mt * 16 * ROWB) + kOff;
                uint32_t ah[4];
                LDMX4(ah[0], ah[1], ah[2], ah[3], tAh + ao);
#pragma unroll
                for (int nt = 0; nt < 4; nt++) {
                    MMA_F16(cfr[mt][nt], ah, bh[nt]);
                    MMA_F16(cfr[mt][nt], ah, bl[nt]);
                }
            }
        }
        __syncthreads();
        if (it + 2 < KITER) load_stage(it + 2, it & 1);
    }

    // Epilogue: c0,c1 -> (row, col..col+1); c2,c3 -> (row+8, col..col+1)
#pragma unroll
    for (int mt = 0; mt < 4; mt++) {
        const int row = mBase + warpM + mt * 16 + gid;
#pragma unroll
        for (int nt = 0; nt < 4; nt++) {
            const int col = nBase + warpN + nt * 8 + tig * 2;
            const float b0 = bias[col], b1 = bias[col + 1];
            float2 v0 = make_float2(cfr[mt][nt][0] + b0, cfr[mt][nt][1] + b1);
            float2 v1 = make_float2(cfr[mt][nt][2] + b0, cfr[mt][nt][3] + b1);
            *reinterpret_cast<float2*>(&C[(size_t)row * ODIM + col]) = v0;
            *reinterpret_cast<float2*>(&C[(size_t)(row + 8) * ODIM + col]) = v1;
        }
    }
}

// ---------------------------------------------------------------------------
// Top-k with exact boundary fixup. One block per row.
//  1. radix-select approx threshold on g_router logits
//  2. logits within +-DELTA rescored EXACTLY (fp64 dot), warp-per-candidate
//  3. keep = above band  U  exact-top of band (exactly KSEL kept)
// fp16x2 router noise sigma ~1.4e-4 -> DELTA = 1.5e-3 is a ~10-sigma band,
// ~4 candidates/row.
// ---------------------------------------------------------------------------
#define DELTA 1.5e-3f
#define MAXC  128

__device__ __forceinline__ unsigned int f2ord(float f) {
    unsigned int b = __float_as_uint(f);
    return (b & 0x80000000u) ? ~b : (b | 0x80000000u);
}

__global__ __launch_bounds__(256)
void topk_fix_kernel(const float* __restrict__ x,
                     const float* __restrict__ Wr,
                     const float* __restrict__ br,
                     float* __restrict__ out)
{
    __shared__ float xrow[DDIM];
    __shared__ unsigned int srow[ODIM];
    __shared__ unsigned char keep[ODIM];
    __shared__ unsigned int hist[256];
    __shared__ int cand_idx[MAXC];
    __shared__ double cscore[MAXC];
    __shared__ unsigned int s_prefix;
    __shared__ int s_kk, s_ncand, s_above, s_extra;
    __shared__ unsigned int s_bhi, s_blo;

    const int row = blockIdx.x;
    const int tid = threadIdx.x;
    const int wid = tid >> 5;
    const int lane = tid & 31;
    const size_t base = (size_t)row * ODIM;

    for (int i = tid; i < DDIM; i += 256)
        xrow[i] = x[(size_t)row * DDIM + i];
    for (int i = tid; i < ODIM; i += 256)
        srow[i] = f2ord(g_router[base + i]);

    if (tid == 0) {
        s_prefix = 0u; s_kk = KSEL;
        s_ncand = 0; s_above = 0; s_extra = 0;
    }
    __syncthreads();

    for (int shift = 24; shift >= 0; shift -= 8) {
        hist[tid] = 0u;
        __syncthreads();
        const unsigned int prefix = s_prefix;
        const unsigned int maskhi = (shift == 24) ? 0u
                                                  : (0xFFFFFFFFu << (shift + 8));
        for (int i = tid; i < ODIM; i += 256) {
            unsigned int u = srow[i];
            if ((u & maskhi) == prefix)
                atomicAdd(&hist[(u >> shift) & 0xFFu], 1u);
        }
        __syncthreads();
        if (tid == 0) {
            int kk = s_kk, cum = 0, b = 255;
            for (; b >= 0; b--) {
                cum += (int)hist[b];
                if (cum >= kk) break;
            }
            s_kk = kk - (cum - (int)hist[b]);
            s_prefix = prefix | ((unsigned int)b << shift);
        }
        __syncthreads();
    }

    const unsigned int thr = s_prefix;
    if (tid == 0) {
        unsigned int b = (thr & 0x80000000u) ? (thr & 0x7FFFFFFFu) : ~thr;
        float vthr = __uint_as_float(b);
        s_bhi = f2ord(vthr + DELTA);
        s_blo = f2ord(vthr - DELTA);
    }
    __syncthreads();
    const unsigned int bhi = s_bhi, blo = s_blo;

    int my_above = 0;
    for (int i = tid; i < ODIM; i += 256) {
        unsigned int u = srow[i];
        if (u > bhi) {
            keep[i] = 1; my_above++;
        } else if (u >= blo) {
            keep[i] = 0;
            int c = atomicAdd(&s_ncand, 1);
            if (c < MAXC) cand_idx[c] = i;
            else if (u >= thr) { keep[i] = 1; atomicAdd(&s_extra, 1); }
        } else {
            keep[i] = 0;
        }
    }
    if (my_above) atomicAdd(&s_above, my_above);
    __syncthreads();

    const int nc = (s_ncand < MAXC) ? s_ncand : MAXC;
    const int n_need = KSEL - s_above - s_extra;

    // Exact fp64 rescoring: one warp per candidate, shfl reduction.
    for (int c = wid; c < nc; c += 8) {
        const int o = cand_idx[c];
        const float* wr = Wr + (size_t)o * DDIM;
        double s = 0.0;
        for (int d = lane; d < DDIM; d += 32)
            s += (double)xrow[d] * (double)wr[d];
#pragma unroll
        for (int off = 16; off > 0; off >>= 1)
            s += __shfl_down_sync(0xFFFFFFFFu, s, off);
        if (lane == 0) cscore[c] = s + (double)br[o];
    }
    __syncthreads();

    if (tid < nc) {
        double mysc = cscore[tid];
        int rank = 0;
        for (int j = 0; j < nc; j++) {
            double sj = cscore[j];
            if (sj > mysc || (sj == mysc && j < tid)) rank++;
        }
        if (rank < n_need) keep[cand_idx[tid]] = 1;
    }
    __syncthreads();

    for (int i = tid; i < ODIM; i += 256) {
        if (!keep[i]) out[base + i] = 0.0f;
    }
}

// ---------------------------------------------------------------------------
// Harness entry point. Device-global scratch never appears here.
// ---------------------------------------------------------------------------
extern "C" void kernel_launch(void* const* d_in, const int* in_sizes, int n_in,
                              void* d_out, int out_size)
{
    const float* x  = (const float*)d_in[0];
    const float* Wr = (const float*)d_in[1];
    const float* br = (const float*)d_in[2];
    const float* Wo = (const float*)d_in[3];
    const float* bo = (const float*)d_in[4];
    float* out = (float*)d_out;

    cudaFuncSetAttribute(gemm_f16x2_kernel,
                         cudaFuncAttributeMaxDynamicSharedMemorySize, GSMEM);

    split_hi_kernel<<<4096, 256>>>(x,  NTOK * DDIM / 4);
    split_hl_kernel<<<4096, 256>>>(Wr, ODIM * DDIM / 4, 1);
    split_hl_kernel<<<4096, 256>>>(Wo, ODIM * DDIM / 4, 2);

    dim3 grid(ODIM / 128, NTOK / 128);
    gemm_f16x2_kernel<<<grid, 256, GSMEM>>>(bo, out, 0);
    gemm_f16x2_kernel<<<grid, 256, GSMEM>>>(br, out, 1);

    topk_fix_kernel<<<NTOK, 256>>>(x, Wr, br, out);
}

// round 15
// speedup vs baseline: 4.9039x; 1.0026x over previous
#include <cuda_runtime.h>
#include <cuda_fp16.h>
#include <cstdint>
#include <cstddef>

// Problem shape (fixed by the reference setup_inputs):
//   x: [8192, 4096] fp32, W_router/W_orig: [4096, 4096] fp32 (row-major, K contiguous)
//   out[n,o] = (x @ W_orig^T)[n,o] * topk_mask(x @ W_router^T)[n,o],  k = 1024 per row
#define NTOK 8192
#define DDIM 4096
#define ODIM 4096
#define KSEL 1024

// ---------------------------------------------------------------------------
// Device-global scratch (allocation-free rule). Referenced ONLY from device
// code — never passed as kernel arguments from host (shadow-address bug, R2-5).
// fp16x2 GEMM: C = hiA*(hiB+loB) = hiA*B_exact; only error is the dropped
// loA*B term (logit sigma ~1.4e-4, deterministic).
// x needs only its hi limb; W needs hi+lo.
// ---------------------------------------------------------------------------
__device__ float  g_router[(size_t)NTOK * ODIM];
__device__ __half g_xh [(size_t)NTOK * DDIM];
__device__ __half g_wrh[(size_t)ODIM * DDIM];
__device__ __half g_wrl[(size_t)ODIM * DDIM];
__device__ __half g_woh[(size_t)ODIM * DDIM];
__device__ __half g_wol[(size_t)ODIM * DDIM];

__device__ __forceinline__ uint32_t smem_u32(const void* p) {
    uint32_t a;
    asm("{ .reg .u64 t; cvta.to.shared.u64 t, %1; cvt.u32.u64 %0, t; }"
        : "=r"(a) : "l"(p));
    return a;
}

// Warp-level fp16 MMA, fp32 accumulate:
// D(16x8,f32) += A(16x16,f16) * B(16x8,f16)
#define MMA_F16(c, a, b) \
    asm volatile( \
        "mma.sync.aligned.m16n8k16.row.col.f32.f16.f16.f32 " \
        "{%0,%1,%2,%3}, {%4,%5,%6,%7}, {%8,%9}, {%0,%1,%2,%3};" \
        : "+f"((c)[0]), "+f"((c)[1]), "+f"((c)[2]), "+f"((c)[3]) \
        : "r"((a)[0]), "r"((a)[1]), "r"((a)[2]), "r"((a)[3]), \
          "r"((b)[0]), "r"((b)[1]))

// 4-matrix ldmatrix: 4 fragment regs per instruction, per-lane row address.
#define LDMX4(r0, r1, r2, r3, addr) \
    asm volatile("ldmatrix.sync.aligned.m8n8.x4.shared.b16 {%0,%1,%2,%3}, [%4];" \
        : "=r"(r0), "=r"(r1), "=r"(r2), "=r"(r3) : "r"(addr))

#define CP_ASYNC16(smem_u32_addr, gptr) \
    asm volatile("cp.async.cg.shared.global [%0], [%1], 16;" \
                 :: "r"(smem_u32_addr), "l"(gptr))
#define CP_COMMIT() asm volatile("cp.async.commit_group;" ::: "memory")
#define CP_WAIT1()  asm volatile("cp.async.wait_group 1;" ::: "memory")

// ---------------------------------------------------------------------------
// Split kernels. Dekker: hi = rn16(v), lo = rn16(v - hi) (v - hi exact fp32).
// ---------------------------------------------------------------------------
struct alignas(8) half4s { __half h[4]; };

// hi-only split for x
__global__ __launch_bounds__(256)
void split_hi_kernel(const float* __restrict__ src, int n4)
{
    __half* hi = g_xh;
    const int stride = gridDim.x * blockDim.x;
    for (int i = blockIdx.x * blockDim.x + threadIdx.x; i < n4; i += stride) {
        float4 v = reinterpret_cast<const float4*>(src)[i];
        half4s H;
        H.h[0] = __float2half_rn(v.x);
        H.h[1] = __float2half_rn(v.y);
        H.h[2] = __float2half_rn(v.z);
        H.h[3] = __float2half_rn(v.w);
        reinterpret_cast<half4s*>(hi)[i] = H;
    }
}

// hi+lo split for weights. which: 1 -> W_router, 2 -> W_orig.
__global__ __launch_bounds__(256)
void split_hl_kernel(const float* __restrict__ src, int n4, int which)
{
    __half *hi, *lo;
    if (which == 1) { hi = g_wrh; lo = g_wrl; }
    else            { hi = g_woh; lo = g_wol; }

    const int stride = gridDim.x * blockDim.x;
    for (int i = blockIdx.x * blockDim.x + threadIdx.x; i < n4; i += stride) {
        float4 v = reinterpret_cast<const float4*>(src)[i];
        half4s H, L;
        H.h[0] = __float2half_rn(v.x);
        H.h[1] = __float2half_rn(v.y);
        H.h[2] = __float2half_rn(v.z);
        H.h[3] = __float2half_rn(v.w);
        L.h[0] = __float2half_rn(v.x - __half2float(H.h[0]));
        L.h[1] = __float2half_rn(v.y - __half2float(H.h[1]));
        L.h[2] = __float2half_rn(v.z - __half2float(H.h[2]));
        L.h[3] = __float2half_rn(v.w - __half2float(H.h[3]));
        reinterpret_cast<half4s*>(hi)[i] = H;
        reinterpret_cast<half4s*>(lo)[i] = L;
    }
}

// ---------------------------------------------------------------------------
// fp16x2 tensor-core GEMM (mma.sync m16n8k16), 3-STAGE circular cp.async
// pipeline (one __syncthreads per K-iter), ldmatrix.x4 fragment loads.
// C = hiA*hiB + hiA*loB (+bias) = hiA*B + bias.
// which: 0 -> W_orig -> outp (d_out);  1 -> W_router -> g_router
// Block tile 128x128, BK=32, 256 threads = 8 warps (2 M x 4 N).
// PADH=40: ldmatrix row stride 80 B -> conflict-free (proven R12-14).
// 90 KB smem/CTA x 2 CTAs/SM = 184 KB < 227 KB -> occupancy 2 retained.
//
// Pipeline safety: the load issued at iteration it targets buf (it+2)%3 =
// the buffer computed at it-1; every warp passed this iteration's
// __syncthreads only after finishing it-1's compute, so the overwrite is
// race-free with a single barrier.
// ---------------------------------------------------------------------------
#define KITER  (DDIM / 32)
#define PADH   40                       // halves per padded row
#define ROWB   (PADH * 2)               // 80 bytes per row
#define TILEH  (128 * PADH)
#define TILEB  (TILEH * 2)              // 10240 B
#define NTH    3                        // tiles per stage: Ah, Bh, Bl
#define STAGEB (NTH * TILEB)            // 30720 B
#define NSTG   3
#define GSMEM  (NSTG * STAGEB)          // 92160 B

__global__ __launch_bounds__(256, 2)
void gemm_f16x2_kernel(const float* __restrict__ bias,
                       float* __restrict__ outp,
                       int which)
{
    extern __shared__ __half smh[];
    const int tid  = threadIdx.x;
    const int wid  = tid >> 5;
    const int lane = tid & 31;
    const int gid  = lane >> 2;
    const int tig  = lane & 3;

    const __half* __restrict__ Ah = g_xh;
    const __half* __restrict__ Bh = (which == 0) ? g_woh : g_wrh;
    const __half* __restrict__ Bl = (which == 0) ? g_wol : g_wrl;
    float* __restrict__ C = (which == 0) ? outp : g_router;

    const int mBase = blockIdx.y * 128;
    const int nBase = blockIdx.x * 128;
    const int warpM = (wid >> 2) * 64;
    const int warpN = (wid & 3) * 32;

    const uint32_t sb = smem_u32(smh);

    // ldmatrix per-lane address components (j = lane/8 selects the matrix)
    const int lj = lane >> 3;
    const int lr = lane & 7;
    const uint32_t aAddrBase =
        (uint32_t)((warpM + ((lj & 1) << 3) + lr) * ROWB + ((lj >> 1) << 4));
    const uint32_t bAddrBase =
        (uint32_t)((warpN + ((lj >> 1) << 3) + lr) * ROWB + ((lj & 1) << 4));

    // slot: 0=Ah 1=Bh 2=Bl. Each tile row: 32 halves (64B) loaded.
    auto load_tile = [&](int buf, int slot, const __half* __restrict__ g,
                         int rowBase, int k0) {
        const uint32_t dst = sb + (uint32_t)buf * STAGEB + (uint32_t)slot * TILEB;
#pragma unroll
        for (int t = 0; t < 2; t++) {
            int idx = tid + t * 256;          // 0..511
            int row = idx >> 2;               // 0..127
            int c   = idx & 3;                // 16B chunk within 64B row
            const __half* src = g + (size_t)(rowBase + row) * DDIM + k0 + c * 8;
            uint32_t d = dst + (uint32_t)(row * ROWB + c * 16);
            CP_ASYNC16(d, src);
        }
    };
    auto load_stage = [&](int it, int buf) {
        const int k0 = it * 32;
        load_tile(buf, 0, Ah, mBase, k0);
        load_tile(buf, 1, Bh, nBase, k0);
        load_tile(buf, 2, Bl, nBase, k0);
        CP_COMMIT();
    };

    float cfr[4][4][4];
#pragma unroll
    for (int mt = 0; mt < 4; mt++)
#pragma unroll
        for (int nt = 0; nt < 4; nt++)
#pragma unroll
            for (int q = 0; q < 4; q++) cfr[mt][nt][q] = 0.0f;

    load_stage(0, 0);
    load_stage(1, 1);

    int bufC = 0;   // compute buffer (= it % 3)
    int bufL = 2;   // next load buffer (= (it+2) % 3)
    for (int it = 0; it < KITER; it++) {
        CP_WAIT1();            // stage it complete (<=1 outstanding group)
        __syncthreads();       // all warps done with buf of it-1; data visible

        // Prefetch stage it+2 into the buffer freed at it-1 (race-free, see top).
        if (it + 2 < KITER) {
            load_stage(it + 2, bufL);
            if (++bufL == NSTG) bufL = 0;
        }

        const uint32_t stg = sb + (uint32_t)bufC * STAGEB;
        const uint32_t tAh = stg;
        const uint32_t tBh = stg + TILEB;
        const uint32_t tBl = stg + 2 * TILEB;

#pragma unroll
        for (int ks = 0; ks < 2; ks++) {          // k16 steps (ks*32 bytes)
            const uint32_t kOff = (uint32_t)(ks << 5);
            uint32_t bh[4][2], bl[4][2];
#pragma unroll
            for (int p = 0; p < 2; p++) {         // nt pairs (0,1) and (2,3)
                const uint32_t bo = bAddrBase + (uint32_t)(p * 16 * ROWB) + kOff;
                LDMX4(bh[2*p][0], bh[2*p][1], bh[2*p+1][0], bh[2*p+1][1], tBh + bo);
                LDMX4(bl[2*p][0], bl[2*p][1], bl[2*p+1][0], bl[2*p+1][1], tBl + bo);
            }
#pragma unroll
            for (int mt = 0; mt < 4; mt++) {
                const uint32_t ao = aAddrBase + (uint32_t)(mt * 16 * ROWB) + kOff;
                uint32_t ah[4];
                LDMX4(ah[0], ah[1], ah[2], ah[3], tAh + ao);
#pragma unroll
                for (int nt = 0; nt < 4; nt++) {
                    MMA_F16(cfr[mt][nt], ah, bh[nt]);
                    MMA_F16(cfr[mt][nt], ah, bl[nt]);
                }
            }
        }
        if (++bufC == NSTG) bufC = 0;
    }

    // Epilogue: c0,c1 -> (row, col..col+1); c2,c3 -> (row+8, col..col+1)
#pragma unroll
    for (int mt = 0; mt < 4; mt++) {
        const int row = mBase + warpM + mt * 16 + gid;
#pragma unroll
        for (int nt = 0; nt < 4; nt++) {
            const int col = nBase + warpN + nt * 8 + tig * 2;
            const float b0 = bias[col], b1 = bias[col + 1];
            float2 v0 = make_float2(cfr[mt][nt][0] + b0, cfr[mt][nt][1] + b1);
            float2 v1 = make_float2(cfr[mt][nt][2] + b0, cfr[mt][nt][3] + b1);
            *reinterpret_cast<float2*>(&C[(size_t)row * ODIM + col]) = v0;
            *reinterpret_cast<float2*>(&C[(size_t)(row + 8) * ODIM + col]) = v1;
        }
    }
}

// ---------------------------------------------------------------------------
// Top-k with exact boundary fixup. One block per row.
//  1. radix-select approx threshold on g_router logits
//  2. logits within +-DELTA rescored EXACTLY (fp64 dot), warp-per-candidate
//  3. keep = above band  U  exact-top of band (exactly KSEL kept)
// fp16x2 router noise sigma ~1.4e-4 -> DELTA = 1.5e-3 is a ~10-sigma band.
// ---------------------------------------------------------------------------
#define DELTA 1.5e-3f
#define MAXC  128

__device__ __forceinline__ unsigned int f2ord(float f) {
    unsigned int b = __float_as_uint(f);
    return (b & 0x80000000u) ? ~b : (b | 0x80000000u);
}

__global__ __launch_bounds__(256)
void topk_fix_kernel(const float* __restrict__ x,
                     const float* __restrict__ Wr,
                     const float* __restrict__ br,
                     float* __restrict__ out)
{
    __shared__ float xrow[DDIM];
    __shared__ unsigned int srow[ODIM];
    __shared__ unsigned char keep[ODIM];
    __shared__ unsigned int hist[256];
    __shared__ int cand_idx[MAXC];
    __shared__ double cscore[MAXC];
    __shared__ unsigned int s_prefix;
    __shared__ int s_kk, s_ncand, s_above, s_extra;
    __shared__ unsigned int s_bhi, s_blo;

    const int row = blockIdx.x;
    const int tid = threadIdx.x;
    const int wid = tid >> 5;
    const int lane = tid & 31;
    const size_t base = (size_t)row * ODIM;

    for (int i = tid; i < DDIM; i += 256)
        xrow[i] = x[(size_t)row * DDIM + i];
    for (int i = tid; i < ODIM; i += 256)
        srow[i] = f2ord(g_router[base + i]);

    if (tid == 0) {
        s_prefix = 0u; s_kk = KSEL;
        s_ncand = 0; s_above = 0; s_extra = 0;
    }
    __syncthreads();

    for (int shift = 24; shift >= 0; shift -= 8) {
        hist[tid] = 0u;
        __syncthreads();
        const unsigned int prefix = s_prefix;
        const unsigned int maskhi = (shift == 24) ? 0u
                                                  : (0xFFFFFFFFu << (shift + 8));
        for (int i = tid; i < ODIM; i += 256) {
            unsigned int u = srow[i];
            if ((u & maskhi) == prefix)
                atomicAdd(&hist[(u >> shift) & 0xFFu], 1u);
        }
        __syncthreads();
        if (tid == 0) {
            int kk = s_kk, cum = 0, b = 255;
            for (; b >= 0; b--) {
                cum += (int)hist[b];
                if (cum >= kk) break;
            }
            s_kk = kk - (cum - (int)hist[b]);
            s_prefix = prefix | ((unsigned int)b << shift);
        }
        __syncthreads();
    }

    const unsigned int thr = s_prefix;
    if (tid == 0) {
        unsigned int b = (thr & 0x80000000u) ? (thr & 0x7FFFFFFFu) : ~thr;
        float vthr = __uint_as_float(b);
        s_bhi = f2ord(vthr + DELTA);
        s_blo = f2ord(vthr - DELTA);
    }
    __syncthreads();
    const unsigned int bhi = s_bhi, blo = s_blo;

    int my_above = 0;
    for (int i = tid; i < ODIM; i += 256) {
        unsigned int u = srow[i];
        if (u > bhi) {
            keep[i] = 1; my_above++;
        } else if (u >= blo) {
            keep[i] = 0;
            int c = atomicAdd(&s_ncand, 1);
            if (c < MAXC) cand_idx[c] = i;
            else if (u >= thr) { keep[i] = 1; atomicAdd(&s_extra, 1); }
        } else {
            keep[i] = 0;
        }
    }
    if (my_above) atomicAdd(&s_above, my_above);
    __syncthreads();

    const int nc = (s_ncand < MAXC) ? s_ncand : MAXC;
    const int n_need = KSEL - s_above - s_extra;

    // Exact fp64 rescoring: one warp per candidate, shfl reduction.
    for (int c = wid; c < nc; c += 8) {
        const int o = cand_idx[c];
        const float* wr = Wr + (size_t)o * DDIM;
        double s = 0.0;
        for (int d = lane; d < DDIM; d += 32)
            s += (double)xrow[d] * (double)wr[d];
#pragma unroll
        for (int off = 16; off > 0; off >>= 1)
            s += __shfl_down_sync(0xFFFFFFFFu, s, off);
        if (lane == 0) cscore[c] = s + (double)br[o];
    }
    __syncthreads();

    if (tid < nc) {
        double mysc = cscore[tid];
        int rank = 0;
        for (int j = 0; j < nc; j++) {
            double sj = cscore[j];
            if (sj > mysc || (sj == mysc && j < tid)) rank++;
        }
        if (rank < n_need) keep[cand_idx[tid]] = 1;
    }
    __syncthreads();

    for (int i = tid; i < ODIM; i += 256) {
        if (!keep[i]) out[base + i] = 0.0f;
    }
}

// ---------------------------------------------------------------------------
// Harness entry point. Device-global scratch never appears here.
// ---------------------------------------------------------------------------
extern "C" void kernel_launch(void* const* d_in, const int* in_sizes, int n_in,
                              void* d_out, int out_size)
{
    const float* x  = (const float*)d_in[0];
    const float* Wr = (const float*)d_in[1];
    const float* br = (const float*)d_in[2];
    const float* Wo = (const float*)d_in[3];
    const float* bo = (const float*)d_in[4];
    float* out = (float*)d_out;

    cudaFuncSetAttribute(gemm_f16x2_kernel,
                         cudaFuncAttributeMaxDynamicSharedMemorySize, GSMEM);

    split_hi_kernel<<<4096, 256>>>(x,  NTOK * DDIM / 4);
    split_hl_kernel<<<4096, 256>>>(Wr, ODIM * DDIM / 4, 1);
    split_hl_kernel<<<4096, 256>>>(Wo, ODIM * DDIM / 4, 2);

    dim3 grid(ODIM / 128, NTOK / 128);
    gemm_f16x2_kernel<<<grid, 256, GSMEM>>>(bo, out, 0);
    gemm_f16x2_kernel<<<grid, 256, GSMEM>>>(br, out, 1);

    topk_fix_kernel<<<NTOK, 256>>>(x, Wr, br, out);
}

// round 16
// speedup vs baseline: 4.9081x; 1.0009x over previous
#include <cuda_runtime.h>
#include <cuda_fp16.h>
#include <cstdint>
#include <cstddef>

// Problem shape (fixed by the reference setup_inputs):
//   x: [8192, 4096] fp32, W_router/W_orig: [4096, 4096] fp32 (row-major, K contiguous)
//   out[n,o] = (x @ W_orig^T)[n,o] * topk_mask(x @ W_router^T)[n,o],  k = 1024 per row
#define NTOK 8192
#define DDIM 4096
#define ODIM 4096
#define KSEL 1024

// ---------------------------------------------------------------------------
// Device-global scratch (allocation-free rule). Referenced ONLY from device
// code — never passed as kernel arguments from host (shadow-address bug, R2-5).
// fp16x2 GEMM: C = hiA*(hiB+loB) = hiA*B_exact; only error is the dropped
// loA*B term (logit sigma ~1.4e-4, deterministic).
// ---------------------------------------------------------------------------
__device__ float  g_router[(size_t)NTOK * ODIM];
__device__ __half g_xh [(size_t)NTOK * DDIM];
__device__ __half g_wrh[(size_t)ODIM * DDIM];
__device__ __half g_wrl[(size_t)ODIM * DDIM];
__device__ __half g_woh[(size_t)ODIM * DDIM];
__device__ __half g_wol[(size_t)ODIM * DDIM];

__device__ __forceinline__ uint32_t smem_u32(const void* p) {
    uint32_t a;
    asm("{ .reg .u64 t; cvta.to.shared.u64 t, %1; cvt.u32.u64 %0, t; }"
        : "=r"(a) : "l"(p));
    return a;
}

// Warp-level fp16 MMA, fp32 accumulate. NOT volatile: pure register
// computation; "+f"/"r" constraints carry all dependencies, so ptxas may
// schedule/software-pipeline independent MMAs (accumulator RAW chains keep
// per-accumulator order, so numerics are bit-identical).
#define MMA_F16(c, a, b) \
    asm( \
        "mma.sync.aligned.m16n8k16.row.col.f32.f16.f16.f32 " \
        "{%0,%1,%2,%3}, {%4,%5,%6,%7}, {%8,%9}, {%0,%1,%2,%3};" \
        : "+f"((c)[0]), "+f"((c)[1]), "+f"((c)[2]), "+f"((c)[3]) \
        : "r"((a)[0]), "r"((a)[1]), "r"((a)[2]), "r"((a)[3]), \
          "r"((b)[0]), "r"((b)[1]))

// 4-matrix ldmatrix: stays volatile (reads smem; must not cross barriers).
#define LDMX4(r0, r1, r2, r3, addr) \
    asm volatile("ldmatrix.sync.aligned.m8n8.x4.shared.b16 {%0,%1,%2,%3}, [%4];" \
        : "=r"(r0), "=r"(r1), "=r"(r2), "=r"(r3) : "r"(addr))

#define CP_ASYNC16(smem_u32_addr, gptr) \
    asm volatile("cp.async.cg.shared.global [%0], [%1], 16;" \
                 :: "r"(smem_u32_addr), "l"(gptr))
#define CP_COMMIT() asm volatile("cp.async.commit_group;" ::: "memory")
#define CP_WAIT1()  asm volatile("cp.async.wait_group 1;" ::: "memory")

// ---------------------------------------------------------------------------
// Split kernels. Dekker: hi = rn16(v), lo = rn16(v - hi) (v - hi exact fp32).
// ---------------------------------------------------------------------------
struct alignas(8) half4s { __half h[4]; };

// hi-only split for x
__global__ __launch_bounds__(256)
void split_hi_kernel(const float* __restrict__ src, int n4)
{
    __half* hi = g_xh;
    const int stride = gridDim.x * blockDim.x;
    for (int i = blockIdx.x * blockDim.x + threadIdx.x; i < n4; i += stride) {
        float4 v = reinterpret_cast<const float4*>(src)[i];
        half4s H;
        H.h[0] = __float2half_rn(v.x);
        H.h[1] = __float2half_rn(v.y);
        H.h[2] = __float2half_rn(v.z);
        H.h[3] = __float2half_rn(v.w);
        reinterpret_cast<half4s*>(hi)[i] = H;
    }
}

// hi+lo split for weights. which: 1 -> W_router, 2 -> W_orig.
__global__ __launch_bounds__(256)
void split_hl_kernel(const float* __restrict__ src, int n4, int which)
{
    __half *hi, *lo;
    if (which == 1) { hi = g_wrh; lo = g_wrl; }
    else            { hi = g_woh; lo = g_wol; }

    const int stride = gridDim.x * blockDim.x;
    for (int i = blockIdx.x * blockDim.x + threadIdx.x; i < n4; i += stride) {
        float4 v = reinterpret_cast<const float4*>(src)[i];
        half4s H, L;
        H.h[0] = __float2half_rn(v.x);
        H.h[1] = __float2half_rn(v.y);
        H.h[2] = __float2half_rn(v.z);
        H.h[3] = __float2half_rn(v.w);
        L.h[0] = __float2half_rn(v.x - __half2float(H.h[0]));
        L.h[1] = __float2half_rn(v.y - __half2float(H.h[1]));
        L.h[2] = __float2half_rn(v.z - __half2float(H.h[2]));
        L.h[3] = __float2half_rn(v.w - __half2float(H.h[3]));
        reinterpret_cast<half4s*>(hi)[i] = H;
        reinterpret_cast<half4s*>(lo)[i] = L;
    }
}

// ---------------------------------------------------------------------------
// fp16x2 tensor-core GEMM (mma.sync m16n8k16), 3-stage circular cp.async
// pipeline, ldmatrix.x4 fragment loads. C = hiA*B + bias.
// MMA ORDERING (R16): per mt, all 4 hh MMAs then all 4 hl MMAs — distinct
// accumulators between consecutive issues (same-acc distance 4, was 1).
// which: 0 -> W_orig -> outp (d_out);  1 -> W_router -> g_router
// Block tile 128x128, BK=32, 256 threads = 8 warps (2 M x 4 N).
// PADH=40 conflict-free (proven R12-15). 90 KB smem/CTA, 2 CTAs/SM.
// ---------------------------------------------------------------------------
#define KITER  (DDIM / 32)
#define PADH   40
#define ROWB   (PADH * 2)               // 80 bytes per row
#define TILEH  (128 * PADH)
#define TILEB  (TILEH * 2)              // 10240 B
#define NTH    3                        // tiles per stage: Ah, Bh, Bl
#define STAGEB (NTH * TILEB)            // 30720 B
#define NSTG   3
#define GSMEM  (NSTG * STAGEB)          // 92160 B

__global__ __launch_bounds__(256, 2)
void gemm_f16x2_kernel(const float* __restrict__ bias,
                       float* __restrict__ outp,
                       int which)
{
    extern __shared__ __half smh[];
    const int tid  = threadIdx.x;
    const int wid  = tid >> 5;
    const int lane = tid & 31;
    const int gid  = lane >> 2;
    const int tig  = lane & 3;

    const __half* __restrict__ Ah = g_xh;
    const __half* __restrict__ Bh = (which == 0) ? g_woh : g_wrh;
    const __half* __restrict__ Bl = (which == 0) ? g_wol : g_wrl;
    float* __restrict__ C = (which == 0) ? outp : g_router;

    const int mBase = blockIdx.y * 128;
    const int nBase = blockIdx.x * 128;
    const int warpM = (wid >> 2) * 64;
    const int warpN = (wid & 3) * 32;

    const uint32_t sb = smem_u32(smh);

    const int lj = lane >> 3;
    const int lr = lane & 7;
    const uint32_t aAddrBase =
        (uint32_t)((warpM + ((lj & 1) << 3) + lr) * ROWB + ((lj >> 1) << 4));
    const uint32_t bAddrBase =
        (uint32_t)((warpN + ((lj >> 1) << 3) + lr) * ROWB + ((lj & 1) << 4));

    auto load_tile = [&](int buf, int slot, const __half* __restrict__ g,
                         int rowBase, int k0) {
        const uint32_t dst = sb + (uint32_t)buf * STAGEB + (uint32_t)slot * TILEB;
#pragma unroll
        for (int t = 0; t < 2; t++) {
            int idx = tid + t * 256;
            int row = idx >> 2;
            int c   = idx & 3;
            const __half* src = g + (size_t)(rowBase + row) * DDIM + k0 + c * 8;
            uint32_t d = dst + (uint32_t)(row * ROWB + c * 16);
            CP_ASYNC16(d, src);
        }
    };
    auto load_stage = [&](int it, int buf) {
        const int k0 = it * 32;
        load_tile(buf, 0, Ah, mBase, k0);
        load_tile(buf, 1, Bh, nBase, k0);
        load_tile(buf, 2, Bl, nBase, k0);
        CP_COMMIT();
    };

    float cfr[4][4][4];
#pragma unroll
    for (int mt = 0; mt < 4; mt++)
#pragma unroll
        for (int nt = 0; nt < 4; nt++)
#pragma unroll
            for (int q = 0; q < 4; q++) cfr[mt][nt][q] = 0.0f;

    load_stage(0, 0);
    load_stage(1, 1);

    int bufC = 0;
    int bufL = 2;
    for (int it = 0; it < KITER; it++) {
        CP_WAIT1();
        __syncthreads();

        if (it + 2 < KITER) {
            load_stage(it + 2, bufL);
            if (++bufL == NSTG) bufL = 0;
        }

        const uint32_t stg = sb + (uint32_t)bufC * STAGEB;
        const uint32_t tAh = stg;
        const uint32_t tBh = stg + TILEB;
        const uint32_t tBl = stg + 2 * TILEB;

#pragma unroll
        for (int ks = 0; ks < 2; ks++) {
            const uint32_t kOff = (uint32_t)(ks << 5);
            uint32_t bh[4][2], bl[4][2];
#pragma unroll
            for (int p = 0; p < 2; p++) {
                const uint32_t bo = bAddrBase + (uint32_t)(p * 16 * ROWB) + kOff;
                LDMX4(bh[2*p][0], bh[2*p][1], bh[2*p+1][0], bh[2*p+1][1], tBh + bo);
                LDMX4(bl[2*p][0], bl[2*p][1], bl[2*p+1][0], bl[2*p+1][1], tBl + bo);
            }
#pragma unroll
            for (int mt = 0; mt < 4; mt++) {
                const uint32_t ao = aAddrBase + (uint32_t)(mt * 16 * ROWB) + kOff;
                uint32_t ah[4];
                LDMX4(ah[0], ah[1], ah[2], ah[3], tAh + ao);
                // hh pass: 4 consecutive MMAs on distinct accumulators
                MMA_F16(cfr[mt][0], ah, bh[0]);
                MMA_F16(cfr[mt][1], ah, bh[1]);
                MMA_F16(cfr[mt][2], ah, bh[2]);
                MMA_F16(cfr[mt][3], ah, bh[3]);
                // hl pass: same-accumulator distance = 4 issues
                MMA_F16(cfr[mt][0], ah, bl[0]);
                MMA_F16(cfr[mt][1], ah, bl[1]);
                MMA_F16(cfr[mt][2], ah, bl[2]);
                MMA_F16(cfr[mt][3], ah, bl[3]);
            }
        }
        if (++bufC == NSTG) bufC = 0;
    }

    // Epilogue: c0,c1 -> (row, col..col+1); c2,c3 -> (row+8, col..col+1)
#pragma unroll
    for (int mt = 0; mt < 4; mt++) {
        const int row = mBase + warpM + mt * 16 + gid;
#pragma unroll
        for (int nt = 0; nt < 4; nt++) {
            const int col = nBase + warpN + nt * 8 + tig * 2;
            const float b0 = bias[col], b1 = bias[col + 1];
            float2 v0 = make_float2(cfr[mt][nt][0] + b0, cfr[mt][nt][1] + b1);
            float2 v1 = make_float2(cfr[mt][nt][2] + b0, cfr[mt][nt][3] + b1);
            *reinterpret_cast<float2*>(&C[(size_t)row * ODIM + col]) = v0;
            *reinterpret_cast<float2*>(&C[(size_t)(row + 8) * ODIM + col]) = v1;
        }
    }
}

// ---------------------------------------------------------------------------
// Top-k with exact boundary fixup. One block per row. (Unchanged, R14-proven.)
// ---------------------------------------------------------------------------
#define DELTA 1.5e-3f
#define MAXC  128

__device__ __forceinline__ unsigned int f2ord(float f) {
    unsigned int b = __float_as_uint(f);
    return (b & 0x80000000u) ? ~b : (b | 0x80000000u);
}

__global__ __launch_bounds__(256)
void topk_fix_kernel(const float* __restrict__ x,
                     const float* __restrict__ Wr,
                     const float* __restrict__ br,
                     float* __restrict__ out)
{
    __shared__ float xrow[DDIM];
    __shared__ unsigned int srow[ODIM];
    __shared__ unsigned char keep[ODIM];
    __shared__ unsigned int hist[256];
    __shared__ int cand_idx[MAXC];
    __shared__ double cscore[MAXC];
    __shared__ unsigned int s_prefix;
    __shared__ int s_kk, s_ncand, s_above, s_extra;
    __shared__ unsigned int s_bhi, s_blo;

    const int row = blockIdx.x;
    const int tid = threadIdx.x;
    const int wid = tid >> 5;
    const int lane = tid & 31;
    const size_t base = (size_t)row * ODIM;

    for (int i = tid; i < DDIM; i += 256)
        xrow[i] = x[(size_t)row * DDIM + i];
    for (int i = tid; i < ODIM; i += 256)
        srow[i] = f2ord(g_router[base + i]);

    if (tid == 0) {
        s_prefix = 0u; s_kk = KSEL;
        s_ncand = 0; s_above = 0; s_extra = 0;
    }
    __syncthreads();

    for (int shift = 24; shift >= 0; shift -= 8) {
        hist[tid] = 0u;
        __syncthreads();
        const unsigned int prefix = s_prefix;
        const unsigned int maskhi = (shift == 24) ? 0u
                                                  : (0xFFFFFFFFu << (shift + 8));
        for (int i = tid; i < ODIM; i += 256) {
            unsigned int u = srow[i];
            if ((u & maskhi) == prefix)
                atomicAdd(&hist[(u >> shift) & 0xFFu], 1u);
        }
        __syncthreads();
        if (tid == 0) {
            int kk = s_kk, cum = 0, b = 255;
            for (; b >= 0; b--) {
                cum += (int)hist[b];
                if (cum >= kk) break;
            }
            s_kk = kk - (cum - (int)hist[b]);
            s_prefix = prefix | ((unsigned int)b << shift);
        }
        __syncthreads();
    }

    const unsigned int thr = s_prefix;
    if (tid == 0) {
        unsigned int b = (thr & 0x80000000u) ? (thr & 0x7FFFFFFFu) : ~thr;
        float vthr = __uint_as_float(b);
        s_bhi = f2ord(vthr + DELTA);
        s_blo = f2ord(vthr - DELTA);
    }
    __syncthreads();
    const unsigned int bhi = s_bhi, blo = s_blo;

    int my_above = 0;
    for (int i = tid; i < ODIM; i += 256) {
        unsigned int u = srow[i];
        if (u > bhi) {
            keep[i] = 1; my_above++;
        } else if (u >= blo) {
            keep[i] = 0;
            int c = atomicAdd(&s_ncand, 1);
            if (c < MAXC) cand_idx[c] = i;
            else if (u >= thr) { keep[i] = 1; atomicAdd(&s_extra, 1); }
        } else {
            keep[i] = 0;
        }
    }
    if (my_above) atomicAdd(&s_above, my_above);
    __syncthreads();

    const int nc = (s_ncand < MAXC) ? s_ncand : MAXC;
    const int n_need = KSEL - s_above - s_extra;

    // Exact fp64 rescoring: one warp per candidate, shfl reduction.
    for (int c = wid; c < nc; c += 8) {
        const int o = cand_idx[c];
        const float* wr = Wr + (size_t)o * DDIM;
        double s = 0.0;
        for (int d = lane; d < DDIM; d += 32)
            s += (double)xrow[d] * (double)wr[d];
#pragma unroll
        for (int off = 16; off > 0; off >>= 1)
            s += __shfl_down_sync(0xFFFFFFFFu, s, off);
        if (lane == 0) cscore[c] = s + (double)br[o];
    }
    __syncthreads();

    if (tid < nc) {
        double mysc = cscore[tid];
        int rank = 0;
        for (int j = 0; j < nc; j++) {
            double sj = cscore[j];
            if (sj > mysc || (sj == mysc && j < tid)) rank++;
        }
        if (rank < n_need) keep[cand_idx[tid]] = 1;
    }
    __syncthreads();

    for (int i = tid; i < ODIM; i += 256) {
        if (!keep[i]) out[base + i] = 0.0f;
    }
}

// ---------------------------------------------------------------------------
// Harness entry point. Device-global scratch never appears here.
// ---------------------------------------------------------------------------
extern "C" void kernel_launch(void* const* d_in, const int* in_sizes, int n_in,
                              void* d_out, int out_size)
{
    const float* x  = (const float*)d_in[0];
    const float* Wr = (const float*)d_in[1];
    const float* br = (const float*)d_in[2];
    const float* Wo = (const float*)d_in[3];
    const float* bo = (const float*)d_in[4];
    float* out = (float*)d_out;

    cudaFuncSetAttribute(gemm_f16x2_kernel,
                         cudaFuncAttributeMaxDynamicSharedMemorySize, GSMEM);

    split_hi_kernel<<<4096, 256>>>(x,  NTOK * DDIM / 4);
    split_hl_kernel<<<4096, 256>>>(Wr, ODIM * DDIM / 4, 1);
    split_hl_kernel<<<4096, 256>>>(Wo, ODIM * DDIM / 4, 2);

    dim3 grid(ODIM / 128, NTOK / 128);
    gemm_f16x2_kernel<<<grid, 256, GSMEM>>>(bo, out, 0);
    gemm_f16x2_kernel<<<grid, 256, GSMEM>>>(br, out, 1);

    topk_fix_kernel<<<NTOK, 256>>>(x, Wr, br, out);
}

// round 17
// speedup vs baseline: 7.6659x; 1.5619x over previous
#include <cuda_runtime.h>
#include <cuda_fp16.h>
#include <cstdint>
#include <cstddef>

// Problem shape (fixed by the reference setup_inputs):
//   x: [8192, 4096] fp32, W_router/W_orig: [4096, 4096] fp32 (row-major, K contiguous)
//   out[n,o] = (x @ W_orig^T)[n,o] * topk_mask(x @ W_router^T)[n,o],  k = 1024 per row
#define NTOK 8192
#define DDIM 4096
#define ODIM 4096
#define KSEL 1024

// ---------------------------------------------------------------------------
// Device-global scratch (allocation-free rule). Referenced ONLY from device
// code — never passed as kernel arguments from host (shadow-address bug, R2-5).
// fp16x1 GEMM: C = hiA*hiB. Dropped terms (loA*B, hiA*loB) have empirically
// calibrated elementwise sigma ~2.1e-4 each (R14 measurement); quadrature
// against the 5.5e-4 reference-noise mask floor stays under 1e-3. The exact
// fp64 top-k fixup (DELTA=2.5e-3 ~ 8 sigma) keeps the mask exact.
// ---------------------------------------------------------------------------
__device__ float  g_router[(size_t)NTOK * ODIM];
__device__ __half g_xh [(size_t)NTOK * DDIM];
__device__ __half g_wrh[(size_t)ODIM * DDIM];
__device__ __half g_woh[(size_t)ODIM * DDIM];

__device__ __forceinline__ uint32_t smem_u32(const void* p) {
    uint32_t a;
    asm("{ .reg .u64 t; cvta.to.shared.u64 t, %1; cvt.u32.u64 %0, t; }"
        : "=r"(a) : "l"(p));
    return a;
}

// Warp-level fp16 MMA, fp32 accumulate. Not volatile: pure register
// computation; constraints carry all dependencies.
#define MMA_F16(c, a, b) \
    asm( \
        "mma.sync.aligned.m16n8k16.row.col.f32.f16.f16.f32 " \
        "{%0,%1,%2,%3}, {%4,%5,%6,%7}, {%8,%9}, {%0,%1,%2,%3};" \
        : "+f"((c)[0]), "+f"((c)[1]), "+f"((c)[2]), "+f"((c)[3]) \
        : "r"((a)[0]), "r"((a)[1]), "r"((a)[2]), "r"((a)[3]), \
          "r"((b)[0]), "r"((b)[1]))

// 4-matrix ldmatrix: stays volatile (reads smem; must not cross barriers).
#define LDMX4(r0, r1, r2, r3, addr) \
    asm volatile("ldmatrix.sync.aligned.m8n8.x4.shared.b16 {%0,%1,%2,%3}, [%4];" \
        : "=r"(r0), "=r"(r1), "=r"(r2), "=r"(r3) : "r"(addr))

#define CP_ASYNC16(smem_u32_addr, gptr) \
    asm volatile("cp.async.cg.shared.global [%0], [%1], 16;" \
                 :: "r"(smem_u32_addr), "l"(gptr))
#define CP_COMMIT() asm volatile("cp.async.commit_group;" ::: "memory")
#define CP_WAIT1()  asm volatile("cp.async.wait_group 1;" ::: "memory")

// ---------------------------------------------------------------------------
// Split kernel: fp32 -> fp16 hi (round-to-nearest, unbiased).
// which: 0 -> x, 1 -> W_router, 2 -> W_orig.
// ---------------------------------------------------------------------------
struct alignas(8) half4s { __half h[4]; };

__global__ __launch_bounds__(256)
void split_hi_kernel(const float* __restrict__ src, int n4, int which)
{
    __half* hi;
    if (which == 0)      hi = g_xh;
    else if (which == 1) hi = g_wrh;
    else                 hi = g_woh;

    const int stride = gridDim.x * blockDim.x;
    for (int i = blockIdx.x * blockDim.x + threadIdx.x; i < n4; i += stride) {
        float4 v = reinterpret_cast<const float4*>(src)[i];
        half4s H;
        H.h[0] = __float2half_rn(v.x);
        H.h[1] = __float2half_rn(v.y);
        H.h[2] = __float2half_rn(v.z);
        H.h[3] = __float2half_rn(v.w);
        reinterpret_cast<half4s*>(hi)[i] = H;
    }
}

// ---------------------------------------------------------------------------
// fp16x1 tensor-core GEMM (mma.sync m16n8k16), 3-stage circular cp.async
// pipeline, ldmatrix.x4 fragment loads. C = hiA*hiB + bias.
// which: 0 -> W_orig -> outp (d_out);  1 -> W_router -> g_router
// Block tile 128x128, BK=32, 256 threads = 8 warps (2 M x 4 N).
// PADH=40 conflict-free (proven R12-16). 48 KB smem/CTA, 2 CTAs/SM.
// ---------------------------------------------------------------------------
#define KITER  (DDIM / 32)
#define PADH   40
#define ROWB   (PADH * 2)               // 80 bytes per row
#define TILEH  (128 * PADH)
#define TILEB  (TILEH * 2)              // 10240 B
#define NTH    2                        // tiles per stage: Ah, Bh
#define STAGEB (NTH * TILEB)            // 20480 B
#define NSTG   3
#define GSMEM  (NSTG * STAGEB)          // 61440 B

__global__ __launch_bounds__(256, 2)
void gemm_f16x1_kernel(const float* __restrict__ bias,
                       float* __restrict__ outp,
                       int which)
{
    extern __shared__ __half smh[];
    const int tid  = threadIdx.x;
    const int wid  = tid >> 5;
    const int lane = tid & 31;
    const int gid  = lane >> 2;
    const int tig  = lane & 3;

    const __half* __restrict__ Ah = g_xh;
    const __half* __restrict__ Bh = (which == 0) ? g_woh : g_wrh;
    float* __restrict__ C = (which == 0) ? outp : g_router;

    const int mBase = blockIdx.y * 128;
    const int nBase = blockIdx.x * 128;
    const int warpM = (wid >> 2) * 64;
    const int warpN = (wid & 3) * 32;

    const uint32_t sb = smem_u32(smh);

    const int lj = lane >> 3;
    const int lr = lane & 7;
    const uint32_t aAddrBase =
        (uint32_t)((warpM + ((lj & 1) << 3) + lr) * ROWB + ((lj >> 1) << 4));
    const uint32_t bAddrBase =
        (uint32_t)((warpN + ((lj >> 1) << 3) + lr) * ROWB + ((lj & 1) << 4));

    auto load_tile = [&](int buf, int slot, const __half* __restrict__ g,
                         int rowBase, int k0) {
        const uint32_t dst = sb + (uint32_t)buf * STAGEB + (uint32_t)slot * TILEB;
#pragma unroll
        for (int t = 0; t < 2; t++) {
            int idx = tid + t * 256;
            int row = idx >> 2;
            int c   = idx & 3;
            const __half* src = g + (size_t)(rowBase + row) * DDIM + k0 + c * 8;
            uint32_t d = dst + (uint32_t)(row * ROWB + c * 16);
            CP_ASYNC16(d, src);
        }
    };
    auto load_stage = [&](int it, int buf) {
        const int k0 = it * 32;
        load_tile(buf, 0, Ah, mBase, k0);
        load_tile(buf, 1, Bh, nBase, k0);
        CP_COMMIT();
    };

    float cfr[4][4][4];
#pragma unroll
    for (int mt = 0; mt < 4; mt++)
#pragma unroll
        for (int nt = 0; nt < 4; nt++)
#pragma unroll
            for (int q = 0; q < 4; q++) cfr[mt][nt][q] = 0.0f;

    load_stage(0, 0);
    load_stage(1, 1);

    int bufC = 0;
    int bufL = 2;
    for (int it = 0; it < KITER; it++) {
        CP_WAIT1();
        __syncthreads();

        if (it + 2 < KITER) {
            load_stage(it + 2, bufL);
            if (++bufL == NSTG) bufL = 0;
        }

        const uint32_t stg = sb + (uint32_t)bufC * STAGEB;
        const uint32_t tAh = stg;
        const uint32_t tBh = stg + TILEB;

#pragma unroll
        for (int ks = 0; ks < 2; ks++) {
            const uint32_t kOff = (uint32_t)(ks << 5);
            uint32_t bh[4][2];
#pragma unroll
            for (int p = 0; p < 2; p++) {
                const uint32_t bo = bAddrBase + (uint32_t)(p * 16 * ROWB) + kOff;
                LDMX4(bh[2*p][0], bh[2*p][1], bh[2*p+1][0], bh[2*p+1][1], tBh + bo);
            }
#pragma unroll
            for (int mt = 0; mt < 4; mt++) {
                const uint32_t ao = aAddrBase + (uint32_t)(mt * 16 * ROWB) + kOff;
                uint32_t ah[4];
                LDMX4(ah[0], ah[1], ah[2], ah[3], tAh + ao);
                MMA_F16(cfr[mt][0], ah, bh[0]);
                MMA_F16(cfr[mt][1], ah, bh[1]);
                MMA_F16(cfr[mt][2], ah, bh[2]);
                MMA_F16(cfr[mt][3], ah, bh[3]);
            }
        }
        if (++bufC == NSTG) bufC = 0;
    }

    // Epilogue: c0,c1 -> (row, col..col+1); c2,c3 -> (row+8, col..col+1)
#pragma unroll
    for (int mt = 0; mt < 4; mt++) {
        const int row = mBase + warpM + mt * 16 + gid;
#pragma unroll
        for (int nt = 0; nt < 4; nt++) {
            const int col = nBase + warpN + nt * 8 + tig * 2;
            const float b0 = bias[col], b1 = bias[col + 1];
            float2 v0 = make_float2(cfr[mt][nt][0] + b0, cfr[mt][nt][1] + b1);
            float2 v1 = make_float2(cfr[mt][nt][2] + b0, cfr[mt][nt][3] + b1);
            *reinterpret_cast<float2*>(&C[(size_t)row * ODIM + col]) = v0;
            *reinterpret_cast<float2*>(&C[(size_t)(row + 8) * ODIM + col]) = v1;
        }
    }
}

// ---------------------------------------------------------------------------
// Top-k with exact boundary fixup. One block per row.
//  1. radix-select approx threshold on g_router logits
//  2. logits within +-DELTA rescored EXACTLY (fp64 dot), warp-per-candidate
//  3. keep = above band  U  exact-top of band (exactly KSEL kept)
// fp16x1 router noise sigma ~3e-4 -> DELTA = 2.5e-3 is a ~8-sigma band,
// ~7 candidates/row.
// ---------------------------------------------------------------------------
#define DELTA 2.5e-3f
#define MAXC  128

__device__ __forceinline__ unsigned int f2ord(float f) {
    unsigned int b = __float_as_uint(f);
    return (b & 0x80000000u) ? ~b : (b | 0x80000000u);
}

__global__ __launch_bounds__(256)
void topk_fix_kernel(const float* __restrict__ x,
                     const float* __restrict__ Wr,
                     const float* __restrict__ br,
                     float* __restrict__ out)
{
    __shared__ float xrow[DDIM];
    __shared__ unsigned int srow[ODIM];
    __shared__ unsigned char keep[ODIM];
    __shared__ unsigned int hist[256];
    __shared__ int cand_idx[MAXC];
    __shared__ double cscore[MAXC];
    __shared__ unsigned int s_prefix;
    __shared__ int s_kk, s_ncand, s_above, s_extra;
    __shared__ unsigned int s_bhi, s_blo;

    const int row = blockIdx.x;
    const int tid = threadIdx.x;
    const int wid = tid >> 5;
    const int lane = tid & 31;
    const size_t base = (size_t)row * ODIM;

    for (int i = tid; i < DDIM; i += 256)
        xrow[i] = x[(size_t)row * DDIM + i];
    for (int i = tid; i < ODIM; i += 256)
        srow[i] = f2ord(g_router[base + i]);

    if (tid == 0) {
        s_prefix = 0u; s_kk = KSEL;
        s_ncand = 0; s_above = 0; s_extra = 0;
    }
    __syncthreads();

    for (int shift = 24; shift >= 0; shift -= 8) {
        hist[tid] = 0u;
        __syncthreads();
        const unsigned int prefix = s_prefix;
        const unsigned int maskhi = (shift == 24) ? 0u
                                                  : (0xFFFFFFFFu << (shift + 8));
        for (int i = tid; i < ODIM; i += 256) {
            unsigned int u = srow[i];
            if ((u & maskhi) == prefix)
                atomicAdd(&hist[(u >> shift) & 0xFFu], 1u);
        }
        __syncthreads();
        if (tid == 0) {
            int kk = s_kk, cum = 0, b = 255;
            for (; b >= 0; b--) {
                cum += (int)hist[b];
                if (cum >= kk) break;
            }
            s_kk = kk - (cum - (int)hist[b]);
            s_prefix = prefix | ((unsigned int)b << shift);
        }
        __syncthreads();
    }

    const unsigned int thr = s_prefix;
    if (tid == 0) {
        unsigned int b = (thr & 0x80000000u) ? (thr & 0x7FFFFFFFu) : ~thr;
        float vthr = __uint_as_float(b);
        s_bhi = f2ord(vthr + DELTA);
        s_blo = f2ord(vthr - DELTA);
    }
    __syncthreads();
    const unsigned int bhi = s_bhi, blo = s_blo;

    int my_above = 0;
    for (int i = tid; i < ODIM; i += 256) {
        unsigned int u = srow[i];
        if (u > bhi) {
            keep[i] = 1; my_above++;
        } else if (u >= blo) {
            keep[i] = 0;
            int c = atomicAdd(&s_ncand, 1);
            if (c < MAXC) cand_idx[c] = i;
            else if (u >= thr) { keep[i] = 1; atomicAdd(&s_extra, 1); }
        } else {
            keep[i] = 0;
        }
    }
    if (my_above) atomicAdd(&s_above, my_above);
    __syncthreads();

    const int nc = (s_ncand < MAXC) ? s_ncand : MAXC;
    const int n_need = KSEL - s_above - s_extra;

    // Exact fp64 rescoring: one warp per candidate, shfl reduction.
    for (int c = wid; c < nc; c += 8) {
        const int o = cand_idx[c];
        const float* wr = Wr + (size_t)o * DDIM;
        double s = 0.0;
        for (int d = lane; d < DDIM; d += 32)
            s += (double)xrow[d] * (double)wr[d];
#pragma unroll
        for (int off = 16; off > 0; off >>= 1)
            s += __shfl_down_sync(0xFFFFFFFFu, s, off);
        if (lane == 0) cscore[c] = s + (double)br[o];
    }
    __syncthreads();

    if (tid < nc) {
        double mysc = cscore[tid];
        int rank = 0;
        for (int j = 0; j < nc; j++) {
            double sj = cscore[j];
            if (sj > mysc || (sj == mysc && j < tid)) rank++;
        }
        if (rank < n_need) keep[cand_idx[tid]] = 1;
    }
    __syncthreads();

    for (int i = tid; i < ODIM; i += 256) {
        if (!keep[i]) out[base + i] = 0.0f;
    }
}

// ---------------------------------------------------------------------------
// Harness entry point. Device-global scratch never appears here.
// ---------------------------------------------------------------------------
extern "C" void kernel_launch(void* const* d_in, const int* in_sizes, int n_in,
                              void* d_out, int out_size)
{
    const float* x  = (const float*)d_in[0];
    const float* Wr = (const float*)d_in[1];
    const float* br = (const float*)d_in[2];
    const float* Wo = (const float*)d_in[3];
    const float* bo = (const float*)d_in[4];
    float* out = (float*)d_out;

    cudaFuncSetAttribute(gemm_f16x1_kernel,
                         cudaFuncAttributeMaxDynamicSharedMemorySize, GSMEM);

    split_hi_kernel<<<4096, 256>>>(x,  NTOK * DDIM / 4, 0);
    split_hi_kernel<<<4096, 256>>>(Wr, ODIM * DDIM / 4, 1);
    split_hi_kernel<<<4096, 256>>>(Wo, ODIM * DDIM / 4, 2);

    dim3 grid(ODIM / 128, NTOK / 128);
    gemm_f16x1_kernel<<<grid, 256, GSMEM>>>(bo, out, 0);
    gemm_f16x1_kernel<<<grid, 256, GSMEM>>>(br, out, 1);

    topk_fix_kernel<<<NTOK, 256>>>(x, Wr, br, out);
}